// round 13
// baseline (speedup 1.0000x reference)
#include <cuda_runtime.h>
#include <cuda_bf16.h>
#include <cuda_fp16.h>
#include <cuda_pipeline.h>
#include <mma.h>
#include <math.h>

// ---------------- Problem constants ----------------
#define T_SEQ  2048
#define BATCH  2
#define NHEADS 16
#define NKVH   4
#define HD     128
#define DIM    2048
#define RANK   512
#define M_ROWS (BATCH * T_SEQ)
#define EPS_F  1.1920928955078125e-07f
#define SCALE_F 0.08838834764831845f

#define NE_MD (M_ROWS * DIM)
#define NE_MR (M_ROWS * RANK)
#define NE_DD (DIM * DIM)
#define NE_RD (RANK * DIM)
#define NE_RR (RANK * RANK)

// ---------------- Scratch (static device globals; no allocation) ----------------
__device__ __half g_xhi[NE_MD];
__device__ __half g_xlo[NE_MD];
__device__ __half g_lhi[NE_MR];
__device__ __half g_llo[NE_MR];
__device__ __half g_yhi[NE_MD];
__device__ __half g_ylo[NE_MD];
__device__ __half g_wqh[NE_DD];
__device__ __half g_wdh[NE_RD];
__device__ __half g_wkh[NE_RR];
__device__ __half g_wvh[NE_RR];
__device__ __half g_wph[NE_DD];

// flash operands: Q fp16 hi/lo, K fp16, V fp16 hi/lo
__device__ __half g_qah[NE_MD];
__device__ __half g_qal[NE_MD];
__device__ __half g_kah[NE_MR];
__device__ __half g_vth[NE_MR];
__device__ __half g_vtl[NE_MR];

// RoPE table: [T_SEQ][64] -> (cos, sin)
__device__ float2 g_rope[T_SEQ * 64];

// ---------------- conversions ----------------
__global__ void split_kernel_h(const float* __restrict__ x,
                               __half* __restrict__ hi,
                               __half* __restrict__ lo, int n)
{
    int i = blockIdx.x * blockDim.x + threadIdx.x;
    if (i < n) {
        float v = x[i];
        __half h = __float2half(v);
        hi[i] = h;
        lo[i] = __float2half(v - __half2float(h));
    }
}

__global__ void conv_kernel_h(const float* __restrict__ x,
                              __half* __restrict__ hi, int n)
{
    int i = blockIdx.x * blockDim.x + threadIdx.x;
    if (i < n) {
        hi[i] = __float2half(x[i]);
    }
}

__global__ void rope_table_kernel()
{
    int i = blockIdx.x * blockDim.x + threadIdx.x;
    if (i < T_SEQ * 64) {
        int t = i >> 6;
        int d = i & 63;
        float fr = powf(10000.0f, -(float)d * (1.0f / 64.0f));
        float ang = (float)t * fr;
        float sn, cs;
        sincosf(ang, &sn, &cs);
        g_rope[i] = make_float2(cs, sn);
    }
}

// ---------------- WMMA fp16x2 GEMM, cp.async 3-stage ----------------
#define GBM 128
#define GBN 128
#define GBK 32
#define GLDS 40
#define GTILE (GBM * GLDS)
#define GSTG (3 * GTILE)
#define GSMEM_BYTES (3 * GSTG * 2)          // 92160
#define STLD 132                            // fp32 stage leading dim (bank-spread)

__device__ __forceinline__ void gemm_stage_load_h(
    __half* s,
    const __half* Ah, const __half* Al, const __half* Bh,
    int bm, int bn, int K, int k0, int tid)
{
    __half* sAh = s;
    __half* sAl = s + GTILE;
    __half* sBh = s + 2 * GTILE;
    for (int i = 0; i < 2; i++) {
        int idx = tid + 256 * i;
        int row = idx >> 2;
        int c8  = (idx & 3) * 8;
        __pipeline_memcpy_async(sAh + row * GLDS + c8,
                                Ah + (size_t)(bm + row) * K + k0 + c8, 16);
        __pipeline_memcpy_async(sAl + row * GLDS + c8,
                                Al + (size_t)(bm + row) * K + k0 + c8, 16);
        __pipeline_memcpy_async(sBh + row * GLDS + c8,
                                Bh + (size_t)(bn + row) * K + k0 + c8, 16);
    }
}

__global__ __launch_bounds__(256) void gemm_h(
    const __half* __restrict__ Ah, const __half* __restrict__ Al,
    const __half* __restrict__ Bh,
    float* __restrict__ C, int M, int N, int K)
{
    extern __shared__ __half gsm[];

    const int tid  = threadIdx.x;
    const int warp = tid / 32;
    const int wm   = (warp % 2) * 64;
    const int wn   = (warp / 2) * 32;
    const int bm   = blockIdx.y * GBM;
    const int bn   = blockIdx.x * GBN;

    nvcuda::wmma::fragment<nvcuda::wmma::accumulator, 16, 16, 16, float> acc[4][2];
    for (int i = 0; i < 4; i++) {
        for (int j = 0; j < 2; j++) {
            nvcuda::wmma::fill_fragment(acc[i][j], 0.0f);
        }
    }

    const int nk = K / GBK;

    gemm_stage_load_h(gsm, Ah, Al, Bh, bm, bn, K, 0, tid);
    __pipeline_commit();
    gemm_stage_load_h(gsm + GSTG, Ah, Al, Bh, bm, bn, K, GBK, tid);
    __pipeline_commit();

    for (int it = 0; it < nk; it++) {
        if (it + 2 < nk) {
            int st = (it + 2) % 3;
            gemm_stage_load_h(gsm + st * GSTG, Ah, Al, Bh, bm, bn, K,
                              (it + 2) * GBK, tid);
            __pipeline_commit();
            __pipeline_wait_prior(2);
        } else if (it + 1 < nk) {
            __pipeline_wait_prior(1);
        } else {
            __pipeline_wait_prior(0);
        }
        __syncthreads();

        __half* sAh = gsm + (it % 3) * GSTG;
        __half* sAl = sAh + GTILE;
        __half* sBh = sAh + 2 * GTILE;

        for (int ks = 0; ks < GBK; ks += 16) {
            nvcuda::wmma::fragment<nvcuda::wmma::matrix_a, 16, 16, 16,
                                   __half, nvcuda::wmma::row_major> fah[4];
            nvcuda::wmma::fragment<nvcuda::wmma::matrix_a, 16, 16, 16,
                                   __half, nvcuda::wmma::row_major> fal[4];
            nvcuda::wmma::fragment<nvcuda::wmma::matrix_b, 16, 16, 16,
                                   __half, nvcuda::wmma::col_major> fbh[2];
            for (int i = 0; i < 4; i++) {
                nvcuda::wmma::load_matrix_sync(fah[i], sAh + (wm + i * 16) * GLDS + ks, GLDS);
                nvcuda::wmma::load_matrix_sync(fal[i], sAl + (wm + i * 16) * GLDS + ks, GLDS);
            }
            for (int j = 0; j < 2; j++) {
                nvcuda::wmma::load_matrix_sync(fbh[j], sBh + (wn + j * 16) * GLDS + ks, GLDS);
            }
            for (int i = 0; i < 4; i++) {
                for (int j = 0; j < 2; j++) {
                    nvcuda::wmma::mma_sync(acc[i][j], fah[i], fbh[j], acc[i][j]);
                    nvcuda::wmma::mma_sync(acc[i][j], fal[i], fbh[j], acc[i][j]);
                }
            }
        }
        __syncthreads();
    }

    for (int i = 0; i < 4; i++) {
        for (int j = 0; j < 2; j++) {
            float* cp = C + (size_t)(bm + wm + i * 16) * N + bn + wn + j * 16;
            nvcuda::wmma::store_matrix_sync(cp, acc[i][j], N, nvcuda::wmma::mem_row_major);
        }
    }
}

// GEMM with epilogue writing fp16 hi/lo (latent + V paths)
__global__ __launch_bounds__(256) void gemm_h_sp16(
    const __half* __restrict__ Ah, const __half* __restrict__ Al,
    const __half* __restrict__ Bh,
    __half* __restrict__ Chi, __half* __restrict__ Clo, int M, int N, int K)
{
    extern __shared__ __half gsm[];

    const int tid  = threadIdx.x;
    const int warp = tid / 32;
    const int wm   = (warp % 2) * 64;
    const int wn   = (warp / 2) * 32;
    const int bm   = blockIdx.y * GBM;
    const int bn   = blockIdx.x * GBN;

    nvcuda::wmma::fragment<nvcuda::wmma::accumulator, 16, 16, 16, float> acc[4][2];
    for (int i = 0; i < 4; i++) {
        for (int j = 0; j < 2; j++) {
            nvcuda::wmma::fill_fragment(acc[i][j], 0.0f);
        }
    }

    const int nk = K / GBK;

    gemm_stage_load_h(gsm, Ah, Al, Bh, bm, bn, K, 0, tid);
    __pipeline_commit();
    gemm_stage_load_h(gsm + GSTG, Ah, Al, Bh, bm, bn, K, GBK, tid);
    __pipeline_commit();

    for (int it = 0; it < nk; it++) {
        if (it + 2 < nk) {
            int st = (it + 2) % 3;
            gemm_stage_load_h(gsm + st * GSTG, Ah, Al, Bh, bm, bn, K,
                              (it + 2) * GBK, tid);
            __pipeline_commit();
            __pipeline_wait_prior(2);
        } else if (it + 1 < nk) {
            __pipeline_wait_prior(1);
        } else {
            __pipeline_wait_prior(0);
        }
        __syncthreads();

        __half* sAh = gsm + (it % 3) * GSTG;
        __half* sAl = sAh + GTILE;
        __half* sBh = sAh + 2 * GTILE;

        for (int ks = 0; ks < GBK; ks += 16) {
            nvcuda::wmma::fragment<nvcuda::wmma::matrix_a, 16, 16, 16,
                                   __half, nvcuda::wmma::row_major> fah[4];
            nvcuda::wmma::fragment<nvcuda::wmma::matrix_a, 16, 16, 16,
                                   __half, nvcuda::wmma::row_major> fal[4];
            nvcuda::wmma::fragment<nvcuda::wmma::matrix_b, 16, 16, 16,
                                   __half, nvcuda::wmma::col_major> fbh[2];
            for (int i = 0; i < 4; i++) {
                nvcuda::wmma::load_matrix_sync(fah[i], sAh + (wm + i * 16) * GLDS + ks, GLDS);
                nvcuda::wmma::load_matrix_sync(fal[i], sAl + (wm + i * 16) * GLDS + ks, GLDS);
            }
            for (int j = 0; j < 2; j++) {
                nvcuda::wmma::load_matrix_sync(fbh[j], sBh + (wn + j * 16) * GLDS + ks, GLDS);
            }
            for (int i = 0; i < 4; i++) {
                for (int j = 0; j < 2; j++) {
                    nvcuda::wmma::mma_sync(acc[i][j], fah[i], fbh[j], acc[i][j]);
                    nvcuda::wmma::mma_sync(acc[i][j], fal[i], fbh[j], acc[i][j]);
                }
            }
        }
        __syncthreads();
    }

    float* stage = (float*)gsm;
    for (int i = 0; i < 4; i++) {
        for (int j = 0; j < 2; j++) {
            nvcuda::wmma::store_matrix_sync(stage + (wm + i * 16) * 128 + wn + j * 16,
                                            acc[i][j], 128, nvcuda::wmma::mem_row_major);
        }
    }
    __syncthreads();
    for (int t = tid; t < GBM * GBN; t += 256) {
        int r = t >> 7;
        int c = t & 127;
        float v = stage[t];
        __half hv = __float2half(v);
        size_t gi = (size_t)(bm + r) * N + bn + c;
        Chi[gi] = hv;
        Clo[gi] = __float2half(v - __half2float(hv));
    }
}

// GEMM with fused RMSNorm + RoPE (+gain) epilogue, RoPE from precomputed table.
__global__ __launch_bounds__(256) void gemm_h_rope(
    const __half* __restrict__ Ah, const __half* __restrict__ Al,
    const __half* __restrict__ Bh,
    __half* __restrict__ dsth, __half* __restrict__ dstl,
    const float* __restrict__ gain, int nheads, int M, int N, int K)
{
    extern __shared__ __half gsm[];

    const int tid  = threadIdx.x;
    const int warp = tid / 32;
    const int wm   = (warp % 2) * 64;
    const int wn   = (warp / 2) * 32;
    const int bm   = blockIdx.y * GBM;
    const int bn   = blockIdx.x * GBN;

    nvcuda::wmma::fragment<nvcuda::wmma::accumulator, 16, 16, 16, float> acc[4][2];
    for (int i = 0; i < 4; i++) {
        for (int j = 0; j < 2; j++) {
            nvcuda::wmma::fill_fragment(acc[i][j], 0.0f);
        }
    }

    const int nk = K / GBK;

    gemm_stage_load_h(gsm, Ah, Al, Bh, bm, bn, K, 0, tid);
    __pipeline_commit();
    gemm_stage_load_h(gsm + GSTG, Ah, Al, Bh, bm, bn, K, GBK, tid);
    __pipeline_commit();

    for (int it = 0; it < nk; it++) {
        if (it + 2 < nk) {
            int st = (it + 2) % 3;
            gemm_stage_load_h(gsm + st * GSTG, Ah, Al, Bh, bm, bn, K,
                              (it + 2) * GBK, tid);
            __pipeline_commit();
            __pipeline_wait_prior(2);
        } else if (it + 1 < nk) {
            __pipeline_wait_prior(1);
        } else {
            __pipeline_wait_prior(0);
        }
        __syncthreads();

        __half* sAh = gsm + (it % 3) * GSTG;
        __half* sAl = sAh + GTILE;
        __half* sBh = sAh + 2 * GTILE;

        for (int ks = 0; ks < GBK; ks += 16) {
            nvcuda::wmma::fragment<nvcuda::wmma::matrix_a, 16, 16, 16,
                                   __half, nvcuda::wmma::row_major> fah[4];
            nvcuda::wmma::fragment<nvcuda::wmma::matrix_a, 16, 16, 16,
                                   __half, nvcuda::wmma::row_major> fal[4];
            nvcuda::wmma::fragment<nvcuda::wmma::matrix_b, 16, 16, 16,
                                   __half, nvcuda::wmma::col_major> fbh[2];
            for (int i = 0; i < 4; i++) {
                nvcuda::wmma::load_matrix_sync(fah[i], sAh + (wm + i * 16) * GLDS + ks, GLDS);
                nvcuda::wmma::load_matrix_sync(fal[i], sAl + (wm + i * 16) * GLDS + ks, GLDS);
            }
            for (int j = 0; j < 2; j++) {
                nvcuda::wmma::load_matrix_sync(fbh[j], sBh + (wn + j * 16) * GLDS + ks, GLDS);
            }
            for (int i = 0; i < 4; i++) {
                for (int j = 0; j < 2; j++) {
                    nvcuda::wmma::mma_sync(acc[i][j], fah[i], fbh[j], acc[i][j]);
                    nvcuda::wmma::mma_sync(acc[i][j], fal[i], fbh[j], acc[i][j]);
                }
            }
        }
        __syncthreads();
    }

    // epilogue: fp32 stage (ld=132), per-row RMS, RoPE from table, gain
    float* stage = (float*)gsm;
    for (int i = 0; i < 4; i++) {
        for (int j = 0; j < 2; j++) {
            nvcuda::wmma::store_matrix_sync(stage + (wm + i * 16) * STLD + wn + j * 16,
                                            acc[i][j], STLD, nvcuda::wmma::mem_row_major);
        }
    }
    __syncthreads();

    const int r    = tid >> 1;          // row 0..127
    const int half = tid & 1;           // 0 or 1
    float ss = 0.f;
    for (int c = half * 64; c < half * 64 + 64; c++) {
        float v = stage[r * STLD + c];
        ss += v * v;
    }
    ss += __shfl_xor_sync(0xffffffffu, ss, 1);
    float rn = rsqrtf(ss * (1.0f / HD) + EPS_F);

    const int m = bm + r;
    const int bb = m / T_SEQ;
    const int t = m % T_SEQ;
    const int head = bn / HD;
    const float g = (gain != 0) ? gain[head] : 1.0f;
    size_t base = ((size_t)(bb * nheads + head) * T_SEQ + t) * HD;
    const float2* rope_t = g_rope + (size_t)t * 64;

    for (int jj = 0; jj < 32; jj++) {
        int d = half * 32 + jj;
        float x1 = stage[r * STLD + d] * rn;
        float x2 = stage[r * STLD + d + 64] * rn;
        float2 cs2 = rope_t[d];
        float v1 = (x1 * cs2.x + x2 * cs2.y) * g;
        float v2 = (x2 * cs2.x - x1 * cs2.y) * g;
        __half h1 = __float2half(v1);
        __half h2 = __float2half(v2);
        dsth[base + d]      = h1;
        dsth[base + 64 + d] = h2;
        if (dstl != 0) {
            dstl[base + d]      = __float2half(v1 - __half2float(h1));
            dstl[base + 64 + d] = __float2half(v2 - __half2float(h2));
        }
    }
}

// ---------------- Flash attention (all fp16 2-pass, fp32 softmax) ----------------
#define FBQ 64
#define FBK 64
#define QLD 136
#define PLD 72
#define SLD 68

#define OQH 0
#define OQL (OQH + FBQ * QLD * 2)
#define OKV (OQL + FBQ * QLD * 2)
#define KVTILE (FBK * QLD * 2)
#define KVSTG (3 * KVTILE)
#define OPH (OKV + 2 * KVSTG)
#define OSF (OPH + FBQ * PLD * 2)
#define OMR (OSF + FBQ * 128 * 4)
#define OLR (OMR + 256)
#define OAR (OLR + 256)
#define FA3_SMEM (OAR + 256)

__device__ __forceinline__ void fa_stage_load(
    char* smb, int s,
    const __half* ksh, const __half* vsh, const __half* vsl, int tid)
{
    char* st = smb + OKV + s * KVSTG;
    __half* sKh = (__half*)st;
    __half* sVh = (__half*)(st + KVTILE);
    __half* sVl = (__half*)(st + 2 * KVTILE);
    for (int i = 0; i < 4; i++) {
        int idx = tid + 256 * i;
        int r = idx >> 4;
        int c = (idx & 15) * 8;
        __pipeline_memcpy_async(sKh + r * QLD + c, ksh + (size_t)r * HD + c, 16);
        __pipeline_memcpy_async(sVh + r * QLD + c, vsh + (size_t)r * RANK + c, 16);
        __pipeline_memcpy_async(sVl + r * QLD + c, vsl + (size_t)r * RANK + c, 16);
    }
}

__global__ __launch_bounds__(256) void flash_mma(
    const __half* __restrict__ Qhi, const __half* __restrict__ Qlo,
    const __half* __restrict__ Khi,
    const __half* __restrict__ Vhi, const __half* __restrict__ Vlo,
    __half* __restrict__ Yh, __half* __restrict__ Yl)
{
    extern __shared__ char smb[];
    __half* sQh = (__half*)(smb + OQH);
    __half* sQl = (__half*)(smb + OQL);
    __half* sPh = (__half*)(smb + OPH);
    float* sSf  = (float*)(smb + OSF);
    float* sOd  = (float*)(smb + OSF);
    float* mrow = (float*)(smb + OMR);
    float* lrow = (float*)(smb + OLR);
    float* arow = (float*)(smb + OAR);

    const int tid  = threadIdx.x;
    const int warp = tid / 32;
    const int qt = (int)(gridDim.x - 1 - blockIdx.x);
    const int h  = blockIdx.y;
    const int b  = blockIdx.z;
    const int kh = h >> 2;
    const int q0 = qt * FBQ;

    const __half* Kh0 = Khi + ((size_t)(b * NKVH + kh) * T_SEQ) * HD;
    const __half* Vh0 = Vhi + (size_t)b * T_SEQ * RANK + kh * HD;
    const __half* Vl0 = Vlo + (size_t)b * T_SEQ * RANK + kh * HD;

    const __half* qsh = Qhi + ((size_t)(b * NHEADS + h) * T_SEQ + q0) * HD;
    const __half* qsl = Qlo + ((size_t)(b * NHEADS + h) * T_SEQ + q0) * HD;
    for (int i = tid; i < FBQ * HD / 8; i += 256) {
        int r = i >> 4;
        int c = (i & 15) * 8;
        *(uint4*)(sQh + r * QLD + c) = *(const uint4*)(qsh + (size_t)r * HD + c);
        *(uint4*)(sQl + r * QLD + c) = *(const uint4*)(qsl + (size_t)r * HD + c);
    }
    if (tid < 64) {
        mrow[tid] = -1e30f;
        lrow[tid] = 0.f;
    }

    float o[32];
#pragma unroll
    for (int j = 0; j < 32; j++) o[j] = 0.f;

    const int ro = tid >> 2;
    const int cq = tid & 3;

    fa_stage_load(smb, 0, Kh0, Vh0, Vl0, tid);
    __pipeline_commit();
    __syncthreads();

    for (int kt = 0; kt <= qt; kt++) {
        const int k0 = kt * FBK;
        if (kt < qt) {
            int k1 = (kt + 1) * FBK;
            fa_stage_load(smb, (kt + 1) & 1,
                          Kh0 + (size_t)k1 * HD,
                          Vh0 + (size_t)k1 * RANK, Vl0 + (size_t)k1 * RANK, tid);
            __pipeline_commit();
            __pipeline_wait_prior(1);
        } else {
            __pipeline_wait_prior(0);
        }
        __syncthreads();

        char* stg = smb + OKV + (size_t)(kt & 1) * KVSTG;
        __half* sKh = (__half*)stg;
        __half* sVh = (__half*)(stg + KVTILE);
        __half* sVl = (__half*)(stg + 2 * KVTILE);

        // ---- S = Q K^T (fp16 2-pass) ----
        {
            const int wm  = warp % 4;
            const int wc0 = (warp / 4) * 2;
            nvcuda::wmma::fragment<nvcuda::wmma::accumulator, 16, 16, 16, float> accs[2];
            for (int j = 0; j < 2; j++) nvcuda::wmma::fill_fragment(accs[j], 0.0f);
            for (int ks = 0; ks < HD; ks += 16) {
                nvcuda::wmma::fragment<nvcuda::wmma::matrix_a, 16, 16, 16,
                                       __half, nvcuda::wmma::row_major> fah;
                nvcuda::wmma::fragment<nvcuda::wmma::matrix_a, 16, 16, 16,
                                       __half, nvcuda::wmma::row_major> fal;
                nvcuda::wmma::load_matrix_sync(fah, sQh + (wm * 16) * QLD + ks, QLD);
                nvcuda::wmma::load_matrix_sync(fal, sQl + (wm * 16) * QLD + ks, QLD);
                for (int j = 0; j < 2; j++) {
                    nvcuda::wmma::fragment<nvcuda::wmma::matrix_b, 16, 16, 16,
                                           __half, nvcuda::wmma::col_major> fbh;
                    nvcuda::wmma::load_matrix_sync(fbh, sKh + ((wc0 + j) * 16) * QLD + ks, QLD);
                    nvcuda::wmma::mma_sync(accs[j], fah, fbh, accs[j]);
                    nvcuda::wmma::mma_sync(accs[j], fal, fbh, accs[j]);
                }
            }
            for (int j = 0; j < 2; j++) {
                nvcuda::wmma::store_matrix_sync(sSf + (wm * 16) * SLD + (wc0 + j) * 16,
                                                accs[j], SLD, nvcuda::wmma::mem_row_major);
            }
        }
        __syncthreads();

        // ---- online softmax ----
        {
            const int r  = tid >> 2;
            const int qq = tid & 3;
            const int qg = q0 + r;
            float mold = mrow[r];
            float vals[16];
            float rmax = mold;
#pragma unroll
            for (int j = 0; j < 16; j++) {
                int c = qq + 4 * j;
                float v = sSf[r * SLD + c] * SCALE_F;
                if (k0 + c > qg) v = -1e30f;
                vals[j] = v;
                rmax = fmaxf(rmax, v);
            }
            rmax = fmaxf(rmax, __shfl_xor_sync(0xffffffffu, rmax, 1));
            rmax = fmaxf(rmax, __shfl_xor_sync(0xffffffffu, rmax, 2));
            float alpha = __expf(mold - rmax);
            float rsum = 0.f;
#pragma unroll
            for (int j = 0; j < 16; j++) {
                int c = qq + 4 * j;
                float p = __expf(vals[j] - rmax);
                sPh[r * PLD + c] = __float2half(p);
                rsum += p;
            }
            rsum += __shfl_xor_sync(0xffffffffu, rsum, 1);
            rsum += __shfl_xor_sync(0xffffffffu, rsum, 2);
            if (qq == 0) {
                lrow[r] = lrow[r] * alpha + rsum;
                mrow[r] = rmax;
                arow[r] = alpha;
            }
        }
        __syncthreads();

        // ---- O_delta = P V (fp16 2-pass) ----
        {
            const int wm  = warp % 4;
            const int wn0 = (warp / 4) * 4;
            nvcuda::wmma::fragment<nvcuda::wmma::accumulator, 16, 16, 16, float> accd[4];
            for (int j = 0; j < 4; j++) nvcuda::wmma::fill_fragment(accd[j], 0.0f);
            for (int kc = 0; kc < FBK; kc += 16) {
                nvcuda::wmma::fragment<nvcuda::wmma::matrix_a, 16, 16, 16,
                                       __half, nvcuda::wmma::row_major> pah;
                nvcuda::wmma::load_matrix_sync(pah, sPh + (wm * 16) * PLD + kc, PLD);
                for (int j = 0; j < 4; j++) {
                    nvcuda::wmma::fragment<nvcuda::wmma::matrix_b, 16, 16, 16,
                                           __half, nvcuda::wmma::row_major> vbh;
                    nvcuda::wmma::fragment<nvcuda::wmma::matrix_b, 16, 16, 16,
                                           __half, nvcuda::wmma::row_major> vbl;
                    nvcuda::wmma::load_matrix_sync(vbh, sVh + kc * QLD + (wn0 + j) * 16, QLD);
                    nvcuda::wmma::load_matrix_sync(vbl, sVl + kc * QLD + (wn0 + j) * 16, QLD);
                    nvcuda::wmma::mma_sync(accd[j], pah, vbh, accd[j]);
                    nvcuda::wmma::mma_sync(accd[j], pah, vbl, accd[j]);
                }
            }
            for (int j = 0; j < 4; j++) {
                nvcuda::wmma::store_matrix_sync(sOd + (wm * 16) * 128 + (wn0 + j) * 16,
                                                accd[j], 128, nvcuda::wmma::mem_row_major);
            }
        }
        __syncthreads();

        {
            float alpha = arow[ro];
            const float* od = sOd + ro * 128 + cq * 32;
#pragma unroll
            for (int j = 0; j < 32; j++) o[j] = o[j] * alpha + od[j];
        }
        __syncthreads();
    }

    float inv = 1.0f / lrow[ro];
    size_t yb = ((size_t)(b * T_SEQ) + q0 + ro) * DIM + h * HD + cq * 32;
#pragma unroll
    for (int j = 0; j < 32; j++) {
        float v = o[j] * inv;
        __half hv = __float2half(v);
        Yh[yb + j] = hv;
        Yl[yb + j] = __float2half(v - __half2float(hv));
    }
}

// ---------------- Launch ----------------
extern "C" void kernel_launch(void* const* d_in, const int* in_sizes, int n_in,
                              void* d_out, int out_size)
{
    (void)in_sizes;
    (void)n_in;
    (void)out_size;
    const float* x     = (const float*)d_in[0];
    const float* Wq    = (const float*)d_in[1];
    const float* Wdown = (const float*)d_in[2];
    const float* Wkup  = (const float*)d_in[3];
    const float* Wvup  = (const float*)d_in[4];
    const float* Wproj = (const float*)d_in[5];
    const float* qgain = (const float*)d_in[6];
    float* out = (float*)d_out;

    __half* xhi;
    __half* xlo;
    __half* lhi;
    __half* llo;
    __half* yhi;
    __half* ylo;
    __half* wqh;
    __half* wdh;
    __half* wkh;
    __half* wvh;
    __half* wph;
    cudaGetSymbolAddress((void**)&xhi, g_xhi);
    cudaGetSymbolAddress((void**)&xlo, g_xlo);
    cudaGetSymbolAddress((void**)&lhi, g_lhi);
    cudaGetSymbolAddress((void**)&llo, g_llo);
    cudaGetSymbolAddress((void**)&yhi, g_yhi);
    cudaGetSymbolAddress((void**)&ylo, g_ylo);
    cudaGetSymbolAddress((void**)&wqh, g_wqh);
    cudaGetSymbolAddress((void**)&wdh, g_wdh);
    cudaGetSymbolAddress((void**)&wkh, g_wkh);
    cudaGetSymbolAddress((void**)&wvh, g_wvh);
    cudaGetSymbolAddress((void**)&wph, g_wph);

    __half* qah;
    __half* qal;
    __half* kah;
    __half* vth;
    __half* vtl;
    cudaGetSymbolAddress((void**)&qah, g_qah);
    cudaGetSymbolAddress((void**)&qal, g_qal);
    cudaGetSymbolAddress((void**)&kah, g_kah);
    cudaGetSymbolAddress((void**)&vth, g_vth);
    cudaGetSymbolAddress((void**)&vtl, g_vtl);

    cudaFuncSetAttribute(gemm_h, cudaFuncAttributeMaxDynamicSharedMemorySize,
                         GSMEM_BYTES);
    cudaFuncSetAttribute(gemm_h_sp16, cudaFuncAttributeMaxDynamicSharedMemorySize,
                         GSMEM_BYTES);
    cudaFuncSetAttribute(gemm_h_rope, cudaFuncAttributeMaxDynamicSharedMemorySize,
                         GSMEM_BYTES);
    cudaFuncSetAttribute(flash_mma, cudaFuncAttributeMaxDynamicSharedMemorySize,
                         FA3_SMEM);

    int n1 = NE_MD;
    int n2 = NE_DD;
    int n3 = NE_RD;
    int n4 = NE_RR;
    int nt = T_SEQ * 64;
    rope_table_kernel<<<(nt + 255) / 256, 256>>>();
    split_kernel_h<<<(n1 + 255) / 256, 256>>>(x, xhi, xlo, n1);
    conv_kernel_h<<<(n2 + 255) / 256, 256>>>(Wq, wqh, n2);
    conv_kernel_h<<<(n3 + 255) / 256, 256>>>(Wdown, wdh, n3);
    conv_kernel_h<<<(n4 + 255) / 256, 256>>>(Wkup, wkh, n4);
    conv_kernel_h<<<(n4 + 255) / 256, 256>>>(Wvup, wvh, n4);
    conv_kernel_h<<<(n2 + 255) / 256, 256>>>(Wproj, wph, n2);

    // latent (fp16 hi/lo epilogue)
    gemm_h_sp16<<<dim3(RANK / GBN, M_ROWS / GBM), 256, GSMEM_BYTES>>>(
        xhi, xlo, wdh, lhi, llo, M_ROWS, RANK, DIM);
    // q projection with fused rmsnorm+rope+gain (table-driven)
    gemm_h_rope<<<dim3(DIM / GBN, M_ROWS / GBM), 256, GSMEM_BYTES>>>(
        xhi, xlo, wqh, qah, qal, qgain, NHEADS, M_ROWS, DIM, DIM);
    // k up-projection with fused rmsnorm+rope (hi only)
    gemm_h_rope<<<dim3(RANK / GBN, M_ROWS / GBM), 256, GSMEM_BYTES>>>(
        lhi, llo, wkh, kah, (__half*)0, (const float*)0, NKVH, M_ROWS, RANK, RANK);
    // v up-projection (fp16 hi/lo epilogue)
    gemm_h_sp16<<<dim3(RANK / GBN, M_ROWS / GBM), 256, GSMEM_BYTES>>>(
        lhi, llo, wvh, vth, vtl, M_ROWS, RANK, RANK);

    flash_mma<<<dim3(T_SEQ / FBQ, NHEADS, BATCH), 256, FA3_SMEM>>>(qah, qal, kah,
                                                                   vth, vtl, yhi, ylo);

    gemm_h<<<dim3(DIM / GBN, M_ROWS / GBM), 256, GSMEM_BYTES>>>(
        yhi, ylo, wph, out, M_ROWS, DIM, DIM);
}

// round 14
// speedup vs baseline: 1.1256x; 1.1256x over previous
#include <cuda_runtime.h>
#include <cuda_bf16.h>
#include <cuda_fp16.h>
#include <cuda_pipeline.h>
#include <mma.h>
#include <math.h>

// ---------------- Problem constants ----------------
#define T_SEQ  2048
#define BATCH  2
#define NHEADS 16
#define NKVH   4
#define HD     128
#define DIM    2048
#define RANK   512
#define M_ROWS (BATCH * T_SEQ)
#define EPS_F  1.1920928955078125e-07f
#define SCALE_F 0.08838834764831845f

#define NE_MD (M_ROWS * DIM)
#define NE_MR (M_ROWS * RANK)
#define NE_DD (DIM * DIM)
#define NE_RD (RANK * DIM)
#define NE_RR (RANK * RANK)

// ---------------- Scratch (static device globals; no allocation) ----------------
__device__ float g_q  [NE_MD];
__device__ float g_kt [NE_MR];
__device__ float g_vt [NE_MR];

__device__ __half g_xhi[NE_MD];
__device__ __half g_xlo[NE_MD];
__device__ __half g_lhi[NE_MR];
__device__ __half g_llo[NE_MR];
__device__ __half g_yhi[NE_MD];
__device__ __half g_ylo[NE_MD];
__device__ __half g_wqh[NE_DD];
__device__ __half g_wdh[NE_RD];
__device__ __half g_wkh[NE_RR];
__device__ __half g_wvh[NE_RR];
__device__ __half g_wph[NE_DD];

// flash operands: Q fp16 hi/lo, K fp16, V fp16 hi/lo
__device__ __half g_qah[NE_MD];
__device__ __half g_qal[NE_MD];
__device__ __half g_kah[NE_MR];
__device__ __half g_vth[NE_MR];
__device__ __half g_vtl[NE_MR];

// RoPE table: [T_SEQ][64] -> (cos, sin)
__device__ float2 g_rope[T_SEQ * 64];

// ---------------- conversions ----------------
__global__ void split_kernel_h(const float* __restrict__ x,
                               __half* __restrict__ hi,
                               __half* __restrict__ lo, int n)
{
    int i = blockIdx.x * blockDim.x + threadIdx.x;
    if (i < n) {
        float v = x[i];
        __half h = __float2half(v);
        hi[i] = h;
        lo[i] = __float2half(v - __half2float(h));
    }
}

__global__ void conv_kernel_h(const float* __restrict__ x,
                              __half* __restrict__ hi, int n)
{
    int i = blockIdx.x * blockDim.x + threadIdx.x;
    if (i < n) {
        hi[i] = __float2half(x[i]);
    }
}

__global__ void rope_table_kernel()
{
    int i = blockIdx.x * blockDim.x + threadIdx.x;
    if (i < T_SEQ * 64) {
        int t = i >> 6;
        int d = i & 63;
        float fr = powf(10000.0f, -(float)d * (1.0f / 64.0f));
        float ang = (float)t * fr;
        float sn, cs;
        sincosf(ang, &sn, &cs);
        g_rope[i] = make_float2(cs, sn);
    }
}

// ---------------- WMMA fp16x2 GEMM, cp.async 2-stage, BK=64 ----------------
#define GBM 128
#define GBN 128
#define GBK 64
#define GLDS 72
#define GTILE (GBM * GLDS)
#define GSTG (3 * GTILE)
#define GSMEM_BYTES (2 * GSTG * 2)          // 110592

__device__ __forceinline__ void gemm_stage_load_h(
    __half* s,
    const __half* Ah, const __half* Al, const __half* Bh,
    int bm, int bn, int K, int k0, int tid)
{
    __half* sAh = s;
    __half* sAl = s + GTILE;
    __half* sBh = s + 2 * GTILE;
    for (int i = 0; i < 4; i++) {
        int idx = tid + 256 * i;
        int row = idx >> 3;
        int c8  = (idx & 7) * 8;
        __pipeline_memcpy_async(sAh + row * GLDS + c8,
                                Ah + (size_t)(bm + row) * K + k0 + c8, 16);
        __pipeline_memcpy_async(sAl + row * GLDS + c8,
                                Al + (size_t)(bm + row) * K + k0 + c8, 16);
        __pipeline_memcpy_async(sBh + row * GLDS + c8,
                                Bh + (size_t)(bn + row) * K + k0 + c8, 16);
    }
}

__global__ __launch_bounds__(256) void gemm_h(
    const __half* __restrict__ Ah, const __half* __restrict__ Al,
    const __half* __restrict__ Bh,
    float* __restrict__ C, int M, int N, int K)
{
    extern __shared__ __half gsm[];

    const int tid  = threadIdx.x;
    const int warp = tid / 32;
    const int wm   = (warp % 2) * 64;
    const int wn   = (warp / 2) * 32;
    const int bm   = blockIdx.y * GBM;
    const int bn   = blockIdx.x * GBN;

    nvcuda::wmma::fragment<nvcuda::wmma::accumulator, 16, 16, 16, float> acc[4][2];
    for (int i = 0; i < 4; i++) {
        for (int j = 0; j < 2; j++) {
            nvcuda::wmma::fill_fragment(acc[i][j], 0.0f);
        }
    }

    const int nk = K / GBK;

    gemm_stage_load_h(gsm, Ah, Al, Bh, bm, bn, K, 0, tid);
    __pipeline_commit();

    for (int it = 0; it < nk; it++) {
        if (it + 1 < nk) {
            gemm_stage_load_h(gsm + ((it + 1) & 1) * GSTG, Ah, Al, Bh, bm, bn, K,
                              (it + 1) * GBK, tid);
            __pipeline_commit();
            __pipeline_wait_prior(1);
        } else {
            __pipeline_wait_prior(0);
        }
        __syncthreads();

        __half* sAh = gsm + (it & 1) * GSTG;
        __half* sAl = sAh + GTILE;
        __half* sBh = sAh + 2 * GTILE;

        for (int ks = 0; ks < GBK; ks += 16) {
            nvcuda::wmma::fragment<nvcuda::wmma::matrix_a, 16, 16, 16,
                                   __half, nvcuda::wmma::row_major> fah[4];
            nvcuda::wmma::fragment<nvcuda::wmma::matrix_a, 16, 16, 16,
                                   __half, nvcuda::wmma::row_major> fal[4];
            nvcuda::wmma::fragment<nvcuda::wmma::matrix_b, 16, 16, 16,
                                   __half, nvcuda::wmma::col_major> fbh[2];
            for (int i = 0; i < 4; i++) {
                nvcuda::wmma::load_matrix_sync(fah[i], sAh + (wm + i * 16) * GLDS + ks, GLDS);
                nvcuda::wmma::load_matrix_sync(fal[i], sAl + (wm + i * 16) * GLDS + ks, GLDS);
            }
            for (int j = 0; j < 2; j++) {
                nvcuda::wmma::load_matrix_sync(fbh[j], sBh + (wn + j * 16) * GLDS + ks, GLDS);
            }
            for (int i = 0; i < 4; i++) {
                for (int j = 0; j < 2; j++) {
                    nvcuda::wmma::mma_sync(acc[i][j], fah[i], fbh[j], acc[i][j]);
                    nvcuda::wmma::mma_sync(acc[i][j], fal[i], fbh[j], acc[i][j]);
                }
            }
        }
        __syncthreads();
    }

    for (int i = 0; i < 4; i++) {
        for (int j = 0; j < 2; j++) {
            float* cp = C + (size_t)(bm + wm + i * 16) * N + bn + wn + j * 16;
            nvcuda::wmma::store_matrix_sync(cp, acc[i][j], N, nvcuda::wmma::mem_row_major);
        }
    }
}

// same GEMM but epilogue writes fp16 hi/lo (latent path)
__global__ __launch_bounds__(256) void gemm_h_sp16(
    const __half* __restrict__ Ah, const __half* __restrict__ Al,
    const __half* __restrict__ Bh,
    __half* __restrict__ Chi, __half* __restrict__ Clo, int M, int N, int K)
{
    extern __shared__ __half gsm[];

    const int tid  = threadIdx.x;
    const int warp = tid / 32;
    const int wm   = (warp % 2) * 64;
    const int wn   = (warp / 2) * 32;
    const int bm   = blockIdx.y * GBM;
    const int bn   = blockIdx.x * GBN;

    nvcuda::wmma::fragment<nvcuda::wmma::accumulator, 16, 16, 16, float> acc[4][2];
    for (int i = 0; i < 4; i++) {
        for (int j = 0; j < 2; j++) {
            nvcuda::wmma::fill_fragment(acc[i][j], 0.0f);
        }
    }

    const int nk = K / GBK;

    gemm_stage_load_h(gsm, Ah, Al, Bh, bm, bn, K, 0, tid);
    __pipeline_commit();

    for (int it = 0; it < nk; it++) {
        if (it + 1 < nk) {
            gemm_stage_load_h(gsm + ((it + 1) & 1) * GSTG, Ah, Al, Bh, bm, bn, K,
                              (it + 1) * GBK, tid);
            __pipeline_commit();
            __pipeline_wait_prior(1);
        } else {
            __pipeline_wait_prior(0);
        }
        __syncthreads();

        __half* sAh = gsm + (it & 1) * GSTG;
        __half* sAl = sAh + GTILE;
        __half* sBh = sAh + 2 * GTILE;

        for (int ks = 0; ks < GBK; ks += 16) {
            nvcuda::wmma::fragment<nvcuda::wmma::matrix_a, 16, 16, 16,
                                   __half, nvcuda::wmma::row_major> fah[4];
            nvcuda::wmma::fragment<nvcuda::wmma::matrix_a, 16, 16, 16,
                                   __half, nvcuda::wmma::row_major> fal[4];
            nvcuda::wmma::fragment<nvcuda::wmma::matrix_b, 16, 16, 16,
                                   __half, nvcuda::wmma::col_major> fbh[2];
            for (int i = 0; i < 4; i++) {
                nvcuda::wmma::load_matrix_sync(fah[i], sAh + (wm + i * 16) * GLDS + ks, GLDS);
                nvcuda::wmma::load_matrix_sync(fal[i], sAl + (wm + i * 16) * GLDS + ks, GLDS);
            }
            for (int j = 0; j < 2; j++) {
                nvcuda::wmma::load_matrix_sync(fbh[j], sBh + (wn + j * 16) * GLDS + ks, GLDS);
            }
            for (int i = 0; i < 4; i++) {
                for (int j = 0; j < 2; j++) {
                    nvcuda::wmma::mma_sync(acc[i][j], fah[i], fbh[j], acc[i][j]);
                    nvcuda::wmma::mma_sync(acc[i][j], fal[i], fbh[j], acc[i][j]);
                }
            }
        }
        __syncthreads();
    }

    float* stage = (float*)gsm;
    for (int i = 0; i < 4; i++) {
        for (int j = 0; j < 2; j++) {
            nvcuda::wmma::store_matrix_sync(stage + (wm + i * 16) * 128 + wn + j * 16,
                                            acc[i][j], 128, nvcuda::wmma::mem_row_major);
        }
    }
    __syncthreads();
    for (int t = tid; t < GBM * GBN; t += 256) {
        int r = t >> 7;
        int c = t & 127;
        float v = stage[t];
        __half hv = __float2half(v);
        size_t gi = (size_t)(bm + r) * N + bn + c;
        Chi[gi] = hv;
        Clo[gi] = __float2half(v - __half2float(hv));
    }
}

// ---------------- RMSNorm + RoPE (+gain), table-driven, fp16 hi (+opt lo) ----------------
__global__ void rms_rope_kernel(const float* __restrict__ src,
                                __half* __restrict__ dsth,
                                __half* __restrict__ dstl,
                                const float* __restrict__ gain, int nheads)
{
    const int m = blockIdx.x;
    const int h = blockIdx.y;
    const int d = threadIdx.x;
    const int b = m / T_SEQ;
    const int t = m % T_SEQ;

    float x = src[(size_t)m * ((size_t)nheads * HD) + h * HD + d];
    float ss = x * x;
#pragma unroll
    for (int o = 16; o > 0; o >>= 1) ss += __shfl_xor_sync(0xffffffffu, ss, o);
    __shared__ float red[4];
    __shared__ float sv[HD];
    if ((d & 31) == 0) red[d >> 5] = ss;
    __syncthreads();
    float tot = red[0] + red[1] + red[2] + red[3];
    float r = rsqrtf(tot * (1.0f / HD) + EPS_F);
    sv[d] = x * r;
    __syncthreads();
    if (d < 64) {
        float x1 = sv[d];
        float x2 = sv[d + 64];
        float2 cs2 = g_rope[(size_t)t * 64 + d];
        float g = (gain != 0) ? gain[h] : 1.0f;
        float v1 = (x1 * cs2.x + x2 * cs2.y) * g;
        float v2 = (x2 * cs2.x - x1 * cs2.y) * g;
        size_t base = ((size_t)(b * nheads + h) * T_SEQ + t) * HD;
        __half h1 = __float2half(v1);
        __half h2 = __float2half(v2);
        dsth[base + d]      = h1;
        dsth[base + 64 + d] = h2;
        if (dstl != 0) {
            dstl[base + d]      = __float2half(v1 - __half2float(h1));
            dstl[base + 64 + d] = __float2half(v2 - __half2float(h2));
        }
    }
}

// ---------------- Flash attention (all fp16 2-pass, fp32 softmax) ----------------
#define FBQ 64
#define FBK 64
#define QLD 136
#define PLD 72
#define SLD 68

#define OQH 0
#define OQL (OQH + FBQ * QLD * 2)
#define OKV (OQL + FBQ * QLD * 2)
#define KVTILE (FBK * QLD * 2)
#define KVSTG (3 * KVTILE)
#define OPH (OKV + 2 * KVSTG)
#define OSF (OPH + FBQ * PLD * 2)
#define OMR (OSF + FBQ * 128 * 4)
#define OLR (OMR + 256)
#define OAR (OLR + 256)
#define FA3_SMEM (OAR + 256)

__device__ __forceinline__ void fa_stage_load(
    char* smb, int s,
    const __half* ksh, const __half* vsh, const __half* vsl, int tid)
{
    char* st = smb + OKV + s * KVSTG;
    __half* sKh = (__half*)st;
    __half* sVh = (__half*)(st + KVTILE);
    __half* sVl = (__half*)(st + 2 * KVTILE);
    for (int i = 0; i < 4; i++) {
        int idx = tid + 256 * i;
        int r = idx >> 4;
        int c = (idx & 15) * 8;
        __pipeline_memcpy_async(sKh + r * QLD + c, ksh + (size_t)r * HD + c, 16);
        __pipeline_memcpy_async(sVh + r * QLD + c, vsh + (size_t)r * RANK + c, 16);
        __pipeline_memcpy_async(sVl + r * QLD + c, vsl + (size_t)r * RANK + c, 16);
    }
}

__global__ __launch_bounds__(256) void flash_mma(
    const __half* __restrict__ Qhi, const __half* __restrict__ Qlo,
    const __half* __restrict__ Khi,
    const __half* __restrict__ Vhi, const __half* __restrict__ Vlo,
    __half* __restrict__ Yh, __half* __restrict__ Yl)
{
    extern __shared__ char smb[];
    __half* sQh = (__half*)(smb + OQH);
    __half* sQl = (__half*)(smb + OQL);
    __half* sPh = (__half*)(smb + OPH);
    float* sSf  = (float*)(smb + OSF);
    float* sOd  = (float*)(smb + OSF);
    float* mrow = (float*)(smb + OMR);
    float* lrow = (float*)(smb + OLR);
    float* arow = (float*)(smb + OAR);

    const int tid  = threadIdx.x;
    const int warp = tid / 32;
    const int qt = (int)(gridDim.x - 1 - blockIdx.x);
    const int h  = blockIdx.y;
    const int b  = blockIdx.z;
    const int kh = h >> 2;
    const int q0 = qt * FBQ;

    const __half* Kh0 = Khi + ((size_t)(b * NKVH + kh) * T_SEQ) * HD;
    const __half* Vh0 = Vhi + (size_t)b * T_SEQ * RANK + kh * HD;
    const __half* Vl0 = Vlo + (size_t)b * T_SEQ * RANK + kh * HD;

    const __half* qsh = Qhi + ((size_t)(b * NHEADS + h) * T_SEQ + q0) * HD;
    const __half* qsl = Qlo + ((size_t)(b * NHEADS + h) * T_SEQ + q0) * HD;
    for (int i = tid; i < FBQ * HD / 8; i += 256) {
        int r = i >> 4;
        int c = (i & 15) * 8;
        *(uint4*)(sQh + r * QLD + c) = *(const uint4*)(qsh + (size_t)r * HD + c);
        *(uint4*)(sQl + r * QLD + c) = *(const uint4*)(qsl + (size_t)r * HD + c);
    }
    if (tid < 64) {
        mrow[tid] = -1e30f;
        lrow[tid] = 0.f;
    }

    float o[32];
#pragma unroll
    for (int j = 0; j < 32; j++) o[j] = 0.f;

    const int ro = tid >> 2;
    const int cq = tid & 3;

    fa_stage_load(smb, 0, Kh0, Vh0, Vl0, tid);
    __pipeline_commit();
    __syncthreads();

    for (int kt = 0; kt <= qt; kt++) {
        const int k0 = kt * FBK;
        if (kt < qt) {
            int k1 = (kt + 1) * FBK;
            fa_stage_load(smb, (kt + 1) & 1,
                          Kh0 + (size_t)k1 * HD,
                          Vh0 + (size_t)k1 * RANK, Vl0 + (size_t)k1 * RANK, tid);
            __pipeline_commit();
            __pipeline_wait_prior(1);
        } else {
            __pipeline_wait_prior(0);
        }
        __syncthreads();

        char* stg = smb + OKV + (size_t)(kt & 1) * KVSTG;
        __half* sKh = (__half*)stg;
        __half* sVh = (__half*)(stg + KVTILE);
        __half* sVl = (__half*)(stg + 2 * KVTILE);

        // ---- S = Q K^T (fp16 2-pass) ----
        {
            const int wm  = warp % 4;
            const int wc0 = (warp / 4) * 2;
            nvcuda::wmma::fragment<nvcuda::wmma::accumulator, 16, 16, 16, float> accs[2];
            for (int j = 0; j < 2; j++) nvcuda::wmma::fill_fragment(accs[j], 0.0f);
            for (int ks = 0; ks < HD; ks += 16) {
                nvcuda::wmma::fragment<nvcuda::wmma::matrix_a, 16, 16, 16,
                                       __half, nvcuda::wmma::row_major> fah;
                nvcuda::wmma::fragment<nvcuda::wmma::matrix_a, 16, 16, 16,
                                       __half, nvcuda::wmma::row_major> fal;
                nvcuda::wmma::load_matrix_sync(fah, sQh + (wm * 16) * QLD + ks, QLD);
                nvcuda::wmma::load_matrix_sync(fal, sQl + (wm * 16) * QLD + ks, QLD);
                for (int j = 0; j < 2; j++) {
                    nvcuda::wmma::fragment<nvcuda::wmma::matrix_b, 16, 16, 16,
                                           __half, nvcuda::wmma::col_major> fbh;
                    nvcuda::wmma::load_matrix_sync(fbh, sKh + ((wc0 + j) * 16) * QLD + ks, QLD);
                    nvcuda::wmma::mma_sync(accs[j], fah, fbh, accs[j]);
                    nvcuda::wmma::mma_sync(accs[j], fal, fbh, accs[j]);
                }
            }
            for (int j = 0; j < 2; j++) {
                nvcuda::wmma::store_matrix_sync(sSf + (wm * 16) * SLD + (wc0 + j) * 16,
                                                accs[j], SLD, nvcuda::wmma::mem_row_major);
            }
        }
        __syncthreads();

        // ---- online softmax ----
        {
            const int r  = tid >> 2;
            const int qq = tid & 3;
            const int qg = q0 + r;
            float mold = mrow[r];
            float vals[16];
            float rmax = mold;
#pragma unroll
            for (int j = 0; j < 16; j++) {
                int c = qq + 4 * j;
                float v = sSf[r * SLD + c] * SCALE_F;
                if (k0 + c > qg) v = -1e30f;
                vals[j] = v;
                rmax = fmaxf(rmax, v);
            }
            rmax = fmaxf(rmax, __shfl_xor_sync(0xffffffffu, rmax, 1));
            rmax = fmaxf(rmax, __shfl_xor_sync(0xffffffffu, rmax, 2));
            float alpha = __expf(mold - rmax);
            float rsum = 0.f;
#pragma unroll
            for (int j = 0; j < 16; j++) {
                int c = qq + 4 * j;
                float p = __expf(vals[j] - rmax);
                sPh[r * PLD + c] = __float2half(p);
                rsum += p;
            }
            rsum += __shfl_xor_sync(0xffffffffu, rsum, 1);
            rsum += __shfl_xor_sync(0xffffffffu, rsum, 2);
            if (qq == 0) {
                lrow[r] = lrow[r] * alpha + rsum;
                mrow[r] = rmax;
                arow[r] = alpha;
            }
        }
        __syncthreads();

        // ---- O_delta = P V (fp16 2-pass) ----
        {
            const int wm  = warp % 4;
            const int wn0 = (warp / 4) * 4;
            nvcuda::wmma::fragment<nvcuda::wmma::accumulator, 16, 16, 16, float> accd[4];
            for (int j = 0; j < 4; j++) nvcuda::wmma::fill_fragment(accd[j], 0.0f);
            for (int kc = 0; kc < FBK; kc += 16) {
                nvcuda::wmma::fragment<nvcuda::wmma::matrix_a, 16, 16, 16,
                                       __half, nvcuda::wmma::row_major> pah;
                nvcuda::wmma::load_matrix_sync(pah, sPh + (wm * 16) * PLD + kc, PLD);
                for (int j = 0; j < 4; j++) {
                    nvcuda::wmma::fragment<nvcuda::wmma::matrix_b, 16, 16, 16,
                                           __half, nvcuda::wmma::row_major> vbh;
                    nvcuda::wmma::fragment<nvcuda::wmma::matrix_b, 16, 16, 16,
                                           __half, nvcuda::wmma::row_major> vbl;
                    nvcuda::wmma::load_matrix_sync(vbh, sVh + kc * QLD + (wn0 + j) * 16, QLD);
                    nvcuda::wmma::load_matrix_sync(vbl, sVl + kc * QLD + (wn0 + j) * 16, QLD);
                    nvcuda::wmma::mma_sync(accd[j], pah, vbh, accd[j]);
                    nvcuda::wmma::mma_sync(accd[j], pah, vbl, accd[j]);
                }
            }
            for (int j = 0; j < 4; j++) {
                nvcuda::wmma::store_matrix_sync(sOd + (wm * 16) * 128 + (wn0 + j) * 16,
                                                accd[j], 128, nvcuda::wmma::mem_row_major);
            }
        }
        __syncthreads();

        {
            float alpha = arow[ro];
            const float* od = sOd + ro * 128 + cq * 32;
#pragma unroll
            for (int j = 0; j < 32; j++) o[j] = o[j] * alpha + od[j];
        }
        __syncthreads();
    }

    float inv = 1.0f / lrow[ro];
    size_t yb = ((size_t)(b * T_SEQ) + q0 + ro) * DIM + h * HD + cq * 32;
#pragma unroll
    for (int j = 0; j < 32; j++) {
        float v = o[j] * inv;
        __half hv = __float2half(v);
        Yh[yb + j] = hv;
        Yl[yb + j] = __float2half(v - __half2float(hv));
    }
}

// ---------------- Launch ----------------
extern "C" void kernel_launch(void* const* d_in, const int* in_sizes, int n_in,
                              void* d_out, int out_size)
{
    (void)in_sizes;
    (void)n_in;
    (void)out_size;
    const float* x     = (const float*)d_in[0];
    const float* Wq    = (const float*)d_in[1];
    const float* Wdown = (const float*)d_in[2];
    const float* Wkup  = (const float*)d_in[3];
    const float* Wvup  = (const float*)d_in[4];
    const float* Wproj = (const float*)d_in[5];
    const float* qgain = (const float*)d_in[6];
    float* out = (float*)d_out;

    float* q;
    float* kt;
    float* vt;
    cudaGetSymbolAddress((void**)&q,  g_q);
    cudaGetSymbolAddress((void**)&kt, g_kt);
    cudaGetSymbolAddress((void**)&vt, g_vt);

    __half* xhi;
    __half* xlo;
    __half* lhi;
    __half* llo;
    __half* yhi;
    __half* ylo;
    __half* wqh;
    __half* wdh;
    __half* wkh;
    __half* wvh;
    __half* wph;
    cudaGetSymbolAddress((void**)&xhi, g_xhi);
    cudaGetSymbolAddress((void**)&xlo, g_xlo);
    cudaGetSymbolAddress((void**)&lhi, g_lhi);
    cudaGetSymbolAddress((void**)&llo, g_llo);
    cudaGetSymbolAddress((void**)&yhi, g_yhi);
    cudaGetSymbolAddress((void**)&ylo, g_ylo);
    cudaGetSymbolAddress((void**)&wqh, g_wqh);
    cudaGetSymbolAddress((void**)&wdh, g_wdh);
    cudaGetSymbolAddress((void**)&wkh, g_wkh);
    cudaGetSymbolAddress((void**)&wvh, g_wvh);
    cudaGetSymbolAddress((void**)&wph, g_wph);

    __half* qah;
    __half* qal;
    __half* kah;
    __half* vth;
    __half* vtl;
    cudaGetSymbolAddress((void**)&qah, g_qah);
    cudaGetSymbolAddress((void**)&qal, g_qal);
    cudaGetSymbolAddress((void**)&kah, g_kah);
    cudaGetSymbolAddress((void**)&vth, g_vth);
    cudaGetSymbolAddress((void**)&vtl, g_vtl);

    cudaFuncSetAttribute(gemm_h, cudaFuncAttributeMaxDynamicSharedMemorySize,
                         GSMEM_BYTES);
    cudaFuncSetAttribute(gemm_h_sp16, cudaFuncAttributeMaxDynamicSharedMemorySize,
                         GSMEM_BYTES);
    cudaFuncSetAttribute(flash_mma, cudaFuncAttributeMaxDynamicSharedMemorySize,
                         FA3_SMEM);

    int n1 = NE_MD;
    int n2 = NE_DD;
    int n3 = NE_RD;
    int n4 = NE_RR;
    int n5 = NE_MR;
    int nt = T_SEQ * 64;
    rope_table_kernel<<<(nt + 255) / 256, 256>>>();
    split_kernel_h<<<(n1 + 255) / 256, 256>>>(x, xhi, xlo, n1);
    conv_kernel_h<<<(n2 + 255) / 256, 256>>>(Wq, wqh, n2);
    conv_kernel_h<<<(n3 + 255) / 256, 256>>>(Wdown, wdh, n3);
    conv_kernel_h<<<(n4 + 255) / 256, 256>>>(Wkup, wkh, n4);
    conv_kernel_h<<<(n4 + 255) / 256, 256>>>(Wvup, wvh, n4);
    conv_kernel_h<<<(n2 + 255) / 256, 256>>>(Wproj, wph, n2);

    gemm_h_sp16<<<dim3(RANK / GBN, M_ROWS / GBM), 256, GSMEM_BYTES>>>(
        xhi, xlo, wdh, lhi, llo, M_ROWS, RANK, DIM);
    gemm_h<<<dim3(DIM / GBN, M_ROWS / GBM), 256, GSMEM_BYTES>>>(
        xhi, xlo, wqh, q, M_ROWS, DIM, DIM);
    gemm_h<<<dim3(RANK / GBN, M_ROWS / GBM), 256, GSMEM_BYTES>>>(
        lhi, llo, wkh, kt, M_ROWS, RANK, RANK);
    gemm_h<<<dim3(RANK / GBN, M_ROWS / GBM), 256, GSMEM_BYTES>>>(
        lhi, llo, wvh, vt, M_ROWS, RANK, RANK);

    rms_rope_kernel<<<dim3(M_ROWS, NHEADS), 128>>>(q, qah, qal, qgain, NHEADS);
    rms_rope_kernel<<<dim3(M_ROWS, NKVH), 128>>>(kt, kah, (__half*)0, (const float*)0, NKVH);
    split_kernel_h<<<(n5 + 255) / 256, 256>>>(vt, vth, vtl, n5);

    flash_mma<<<dim3(T_SEQ / FBQ, NHEADS, BATCH), 256, FA3_SMEM>>>(qah, qal, kah,
                                                                   vth, vtl, yhi, ylo);

    gemm_h<<<dim3(DIM / GBN, M_ROWS / GBM), 256, GSMEM_BYTES>>>(
        yhi, ylo, wph, out, M_ROWS, DIM, DIM);
}

// round 15
// speedup vs baseline: 1.1438x; 1.0162x over previous
#include <cuda_runtime.h>
#include <cuda_bf16.h>
#include <cuda_fp16.h>
#include <cuda_pipeline.h>
#include <mma.h>
#include <math.h>

// ---------------- Problem constants ----------------
#define T_SEQ  2048
#define BATCH  2
#define NHEADS 16
#define NKVH   4
#define HD     128
#define DIM    2048
#define RANK   512
#define M_ROWS (BATCH * T_SEQ)
#define EPS_F  1.1920928955078125e-07f
#define SCALE_F 0.08838834764831845f

#define NE_MD (M_ROWS * DIM)
#define NE_MR (M_ROWS * RANK)
#define NE_DD (DIM * DIM)
#define NE_RD (RANK * DIM)
#define NE_RR (RANK * RANK)

// ---------------- Scratch (static device globals; no allocation) ----------------
__device__ float g_q  [NE_MD];
__device__ float g_kt [NE_MR];

__device__ __half g_xhi[NE_MD];
__device__ __half g_xlo[NE_MD];
__device__ __half g_lhi[NE_MR];
__device__ __half g_llo[NE_MR];
__device__ __half g_yhi[NE_MD];
__device__ __half g_ylo[NE_MD];
__device__ __half g_wqd[NE_DD + NE_RD];   // Wq rows then Wdown rows, [2560 x 2048]
__device__ __half g_wkv[2 * NE_RR];       // Wkup rows then Wvup rows, [1024 x 512]
__device__ __half g_wph[NE_DD];

// flash operands: Q fp16 hi/lo, K fp16, V fp16 hi/lo
__device__ __half g_qah[NE_MD];
__device__ __half g_qal[NE_MD];
__device__ __half g_kah[NE_MR];
__device__ __half g_vth[NE_MR];
__device__ __half g_vtl[NE_MR];

// RoPE table: [T_SEQ][64] -> (cos, sin)
__device__ float2 g_rope[T_SEQ * 64];

// ---------------- conversions ----------------
__global__ void split_kernel_h(const float* __restrict__ x,
                               __half* __restrict__ hi,
                               __half* __restrict__ lo, int n)
{
    int i = blockIdx.x * blockDim.x + threadIdx.x;
    if (i < n) {
        float v = x[i];
        __half h = __float2half(v);
        hi[i] = h;
        lo[i] = __float2half(v - __half2float(h));
    }
}

__global__ void conv_kernel_h(const float* __restrict__ x,
                              __half* __restrict__ hi, int n)
{
    int i = blockIdx.x * blockDim.x + threadIdx.x;
    if (i < n) {
        hi[i] = __float2half(x[i]);
    }
}

__global__ void rope_table_kernel()
{
    int i = blockIdx.x * blockDim.x + threadIdx.x;
    if (i < T_SEQ * 64) {
        int t = i >> 6;
        int d = i & 63;
        float fr = powf(10000.0f, -(float)d * (1.0f / 64.0f));
        float ang = (float)t * fr;
        float sn, cs;
        sincosf(ang, &sn, &cs);
        g_rope[i] = make_float2(cs, sn);
    }
}

// ---------------- WMMA fp16x2 GEMM, cp.async 2-stage, BK=64 ----------------
#define GBM 128
#define GBN 128
#define GBK 64
#define GLDS 72
#define GTILE (GBM * GLDS)
#define GSTG (3 * GTILE)
#define GSMEM_BYTES (2 * GSTG * 2)          // 110592

__device__ __forceinline__ void gemm_stage_load_h(
    __half* s,
    const __half* Ah, const __half* Al, const __half* Bh,
    int bm, int bn, int K, int k0, int tid)
{
    __half* sAh = s;
    __half* sAl = s + GTILE;
    __half* sBh = s + 2 * GTILE;
    for (int i = 0; i < 4; i++) {
        int idx = tid + 256 * i;
        int row = idx >> 3;
        int c8  = (idx & 7) * 8;
        __pipeline_memcpy_async(sAh + row * GLDS + c8,
                                Ah + (size_t)(bm + row) * K + k0 + c8, 16);
        __pipeline_memcpy_async(sAl + row * GLDS + c8,
                                Al + (size_t)(bm + row) * K + k0 + c8, 16);
        __pipeline_memcpy_async(sBh + row * GLDS + c8,
                                Bh + (size_t)(bn + row) * K + k0 + c8, 16);
    }
}

// plain GEMM, fp32 output (Wproj)
__global__ __launch_bounds__(256) void gemm_h(
    const __half* __restrict__ Ah, const __half* __restrict__ Al,
    const __half* __restrict__ Bh,
    float* __restrict__ C, int M, int N, int K)
{
    extern __shared__ __half gsm[];

    const int tid  = threadIdx.x;
    const int warp = tid / 32;
    const int wm   = (warp % 2) * 64;
    const int wn   = (warp / 2) * 32;
    const int bm   = blockIdx.y * GBM;
    const int bn   = blockIdx.x * GBN;

    nvcuda::wmma::fragment<nvcuda::wmma::accumulator, 16, 16, 16, float> acc[4][2];
    for (int i = 0; i < 4; i++) {
        for (int j = 0; j < 2; j++) {
            nvcuda::wmma::fill_fragment(acc[i][j], 0.0f);
        }
    }

    const int nk = K / GBK;

    gemm_stage_load_h(gsm, Ah, Al, Bh, bm, bn, K, 0, tid);
    __pipeline_commit();

    for (int it = 0; it < nk; it++) {
        if (it + 1 < nk) {
            gemm_stage_load_h(gsm + ((it + 1) & 1) * GSTG, Ah, Al, Bh, bm, bn, K,
                              (it + 1) * GBK, tid);
            __pipeline_commit();
            __pipeline_wait_prior(1);
        } else {
            __pipeline_wait_prior(0);
        }
        __syncthreads();

        __half* sAh = gsm + (it & 1) * GSTG;
        __half* sAl = sAh + GTILE;
        __half* sBh = sAh + 2 * GTILE;

        for (int ks = 0; ks < GBK; ks += 16) {
            nvcuda::wmma::fragment<nvcuda::wmma::matrix_a, 16, 16, 16,
                                   __half, nvcuda::wmma::row_major> fah[4];
            nvcuda::wmma::fragment<nvcuda::wmma::matrix_a, 16, 16, 16,
                                   __half, nvcuda::wmma::row_major> fal[4];
            nvcuda::wmma::fragment<nvcuda::wmma::matrix_b, 16, 16, 16,
                                   __half, nvcuda::wmma::col_major> fbh[2];
            for (int i = 0; i < 4; i++) {
                nvcuda::wmma::load_matrix_sync(fah[i], sAh + (wm + i * 16) * GLDS + ks, GLDS);
                nvcuda::wmma::load_matrix_sync(fal[i], sAl + (wm + i * 16) * GLDS + ks, GLDS);
            }
            for (int j = 0; j < 2; j++) {
                nvcuda::wmma::load_matrix_sync(fbh[j], sBh + (wn + j * 16) * GLDS + ks, GLDS);
            }
            for (int i = 0; i < 4; i++) {
                for (int j = 0; j < 2; j++) {
                    nvcuda::wmma::mma_sync(acc[i][j], fah[i], fbh[j], acc[i][j]);
                    nvcuda::wmma::mma_sync(acc[i][j], fal[i], fbh[j], acc[i][j]);
                }
            }
        }
        __syncthreads();
    }

    for (int i = 0; i < 4; i++) {
        for (int j = 0; j < 2; j++) {
            float* cp = C + (size_t)(bm + wm + i * 16) * N + bn + wn + j * 16;
            nvcuda::wmma::store_matrix_sync(cp, acc[i][j], N, nvcuda::wmma::mem_row_major);
        }
    }
}

// Merged GEMM: column blocks below Nsplit write fp32 (ld ldf); blocks at/above
// Nsplit write fp16 hi/lo at col (bn - Nsplit) with ld ldh.
__global__ __launch_bounds__(256) void gemm_h_mix(
    const __half* __restrict__ Ah, const __half* __restrict__ Al,
    const __half* __restrict__ Bh,
    float* __restrict__ Cf, __half* __restrict__ Chi, __half* __restrict__ Clo,
    int M, int N, int K, int Nsplit, int ldf, int ldh)
{
    extern __shared__ __half gsm[];

    const int tid  = threadIdx.x;
    const int warp = tid / 32;
    const int wm   = (warp % 2) * 64;
    const int wn   = (warp / 2) * 32;
    const int bm   = blockIdx.y * GBM;
    const int bn   = blockIdx.x * GBN;

    nvcuda::wmma::fragment<nvcuda::wmma::accumulator, 16, 16, 16, float> acc[4][2];
    for (int i = 0; i < 4; i++) {
        for (int j = 0; j < 2; j++) {
            nvcuda::wmma::fill_fragment(acc[i][j], 0.0f);
        }
    }

    const int nk = K / GBK;

    gemm_stage_load_h(gsm, Ah, Al, Bh, bm, bn, K, 0, tid);
    __pipeline_commit();

    for (int it = 0; it < nk; it++) {
        if (it + 1 < nk) {
            gemm_stage_load_h(gsm + ((it + 1) & 1) * GSTG, Ah, Al, Bh, bm, bn, K,
                              (it + 1) * GBK, tid);
            __pipeline_commit();
            __pipeline_wait_prior(1);
        } else {
            __pipeline_wait_prior(0);
        }
        __syncthreads();

        __half* sAh = gsm + (it & 1) * GSTG;
        __half* sAl = sAh + GTILE;
        __half* sBh = sAh + 2 * GTILE;

        for (int ks = 0; ks < GBK; ks += 16) {
            nvcuda::wmma::fragment<nvcuda::wmma::matrix_a, 16, 16, 16,
                                   __half, nvcuda::wmma::row_major> fah[4];
            nvcuda::wmma::fragment<nvcuda::wmma::matrix_a, 16, 16, 16,
                                   __half, nvcuda::wmma::row_major> fal[4];
            nvcuda::wmma::fragment<nvcuda::wmma::matrix_b, 16, 16, 16,
                                   __half, nvcuda::wmma::col_major> fbh[2];
            for (int i = 0; i < 4; i++) {
                nvcuda::wmma::load_matrix_sync(fah[i], sAh + (wm + i * 16) * GLDS + ks, GLDS);
                nvcuda::wmma::load_matrix_sync(fal[i], sAl + (wm + i * 16) * GLDS + ks, GLDS);
            }
            for (int j = 0; j < 2; j++) {
                nvcuda::wmma::load_matrix_sync(fbh[j], sBh + (wn + j * 16) * GLDS + ks, GLDS);
            }
            for (int i = 0; i < 4; i++) {
                for (int j = 0; j < 2; j++) {
                    nvcuda::wmma::mma_sync(acc[i][j], fah[i], fbh[j], acc[i][j]);
                    nvcuda::wmma::mma_sync(acc[i][j], fal[i], fbh[j], acc[i][j]);
                }
            }
        }
        __syncthreads();
    }

    if (bn < Nsplit) {
        for (int i = 0; i < 4; i++) {
            for (int j = 0; j < 2; j++) {
                float* cp = Cf + (size_t)(bm + wm + i * 16) * ldf + bn + wn + j * 16;
                nvcuda::wmma::store_matrix_sync(cp, acc[i][j], ldf,
                                                nvcuda::wmma::mem_row_major);
            }
        }
    } else {
        float* stage = (float*)gsm;
        for (int i = 0; i < 4; i++) {
            for (int j = 0; j < 2; j++) {
                nvcuda::wmma::store_matrix_sync(stage + (wm + i * 16) * 128 + wn + j * 16,
                                                acc[i][j], 128, nvcuda::wmma::mem_row_major);
            }
        }
        __syncthreads();
        int cb = bn - Nsplit;
        for (int t = tid; t < GBM * GBN; t += 256) {
            int r = t >> 7;
            int c = t & 127;
            float v = stage[t];
            __half hv = __float2half(v);
            size_t gi = (size_t)(bm + r) * ldh + cb + c;
            Chi[gi] = hv;
            Clo[gi] = __float2half(v - __half2float(hv));
        }
    }
}

// ---------------- RMSNorm + RoPE (+gain), table-driven, fp16 hi (+opt lo) ----------------
__global__ void rms_rope_kernel(const float* __restrict__ src,
                                __half* __restrict__ dsth,
                                __half* __restrict__ dstl,
                                const float* __restrict__ gain, int nheads)
{
    const int m = blockIdx.x;
    const int h = blockIdx.y;
    const int d = threadIdx.x;
    const int b = m / T_SEQ;
    const int t = m % T_SEQ;

    float x = src[(size_t)m * ((size_t)nheads * HD) + h * HD + d];
    float ss = x * x;
#pragma unroll
    for (int o = 16; o > 0; o >>= 1) ss += __shfl_xor_sync(0xffffffffu, ss, o);
    __shared__ float red[4];
    __shared__ float sv[HD];
    if ((d & 31) == 0) red[d >> 5] = ss;
    __syncthreads();
    float tot = red[0] + red[1] + red[2] + red[3];
    float r = rsqrtf(tot * (1.0f / HD) + EPS_F);
    sv[d] = x * r;
    __syncthreads();
    if (d < 64) {
        float x1 = sv[d];
        float x2 = sv[d + 64];
        float2 cs2 = g_rope[(size_t)t * 64 + d];
        float g = (gain != 0) ? gain[h] : 1.0f;
        float v1 = (x1 * cs2.x + x2 * cs2.y) * g;
        float v2 = (x2 * cs2.x - x1 * cs2.y) * g;
        size_t base = ((size_t)(b * nheads + h) * T_SEQ + t) * HD;
        __half h1 = __float2half(v1);
        __half h2 = __float2half(v2);
        dsth[base + d]      = h1;
        dsth[base + 64 + d] = h2;
        if (dstl != 0) {
            dstl[base + d]      = __float2half(v1 - __half2float(h1));
            dstl[base + 64 + d] = __float2half(v2 - __half2float(h2));
        }
    }
}

// ---------------- Flash attention (all fp16 2-pass, fp32 softmax) ----------------
#define FBQ 64
#define FBK 64
#define QLD 136
#define PLD 72
#define SLD 68

#define OQH 0
#define OQL (OQH + FBQ * QLD * 2)
#define OKV (OQL + FBQ * QLD * 2)
#define KVTILE (FBK * QLD * 2)
#define KVSTG (3 * KVTILE)
#define OPH (OKV + 2 * KVSTG)
#define OSF (OPH + FBQ * PLD * 2)
#define OMR (OSF + FBQ * 128 * 4)
#define OLR (OMR + 256)
#define OAR (OLR + 256)
#define FA3_SMEM (OAR + 256)

__device__ __forceinline__ void fa_stage_load(
    char* smb, int s,
    const __half* ksh, const __half* vsh, const __half* vsl, int tid)
{
    char* st = smb + OKV + s * KVSTG;
    __half* sKh = (__half*)st;
    __half* sVh = (__half*)(st + KVTILE);
    __half* sVl = (__half*)(st + 2 * KVTILE);
    for (int i = 0; i < 4; i++) {
        int idx = tid + 256 * i;
        int r = idx >> 4;
        int c = (idx & 15) * 8;
        __pipeline_memcpy_async(sKh + r * QLD + c, ksh + (size_t)r * HD + c, 16);
        __pipeline_memcpy_async(sVh + r * QLD + c, vsh + (size_t)r * RANK + c, 16);
        __pipeline_memcpy_async(sVl + r * QLD + c, vsl + (size_t)r * RANK + c, 16);
    }
}

__global__ __launch_bounds__(256) void flash_mma(
    const __half* __restrict__ Qhi, const __half* __restrict__ Qlo,
    const __half* __restrict__ Khi,
    const __half* __restrict__ Vhi, const __half* __restrict__ Vlo,
    __half* __restrict__ Yh, __half* __restrict__ Yl)
{
    extern __shared__ char smb[];
    __half* sQh = (__half*)(smb + OQH);
    __half* sQl = (__half*)(smb + OQL);
    __half* sPh = (__half*)(smb + OPH);
    float* sSf  = (float*)(smb + OSF);
    float* sOd  = (float*)(smb + OSF);
    float* mrow = (float*)(smb + OMR);
    float* lrow = (float*)(smb + OLR);
    float* arow = (float*)(smb + OAR);

    const int tid  = threadIdx.x;
    const int warp = tid / 32;
    const int qt = (int)(gridDim.x - 1 - blockIdx.x);
    const int h  = blockIdx.y;
    const int b  = blockIdx.z;
    const int kh = h >> 2;
    const int q0 = qt * FBQ;

    const __half* Kh0 = Khi + ((size_t)(b * NKVH + kh) * T_SEQ) * HD;
    const __half* Vh0 = Vhi + (size_t)b * T_SEQ * RANK + kh * HD;
    const __half* Vl0 = Vlo + (size_t)b * T_SEQ * RANK + kh * HD;

    const __half* qsh = Qhi + ((size_t)(b * NHEADS + h) * T_SEQ + q0) * HD;
    const __half* qsl = Qlo + ((size_t)(b * NHEADS + h) * T_SEQ + q0) * HD;
    for (int i = tid; i < FBQ * HD / 8; i += 256) {
        int r = i >> 4;
        int c = (i & 15) * 8;
        *(uint4*)(sQh + r * QLD + c) = *(const uint4*)(qsh + (size_t)r * HD + c);
        *(uint4*)(sQl + r * QLD + c) = *(const uint4*)(qsl + (size_t)r * HD + c);
    }
    if (tid < 64) {
        mrow[tid] = -1e30f;
        lrow[tid] = 0.f;
    }

    float o[32];
#pragma unroll
    for (int j = 0; j < 32; j++) o[j] = 0.f;

    const int ro = tid >> 2;
    const int cq = tid & 3;

    fa_stage_load(smb, 0, Kh0, Vh0, Vl0, tid);
    __pipeline_commit();
    __syncthreads();

    for (int kt = 0; kt <= qt; kt++) {
        const int k0 = kt * FBK;
        if (kt < qt) {
            int k1 = (kt + 1) * FBK;
            fa_stage_load(smb, (kt + 1) & 1,
                          Kh0 + (size_t)k1 * HD,
                          Vh0 + (size_t)k1 * RANK, Vl0 + (size_t)k1 * RANK, tid);
            __pipeline_commit();
            __pipeline_wait_prior(1);
        } else {
            __pipeline_wait_prior(0);
        }
        __syncthreads();

        char* stg = smb + OKV + (size_t)(kt & 1) * KVSTG;
        __half* sKh = (__half*)stg;
        __half* sVh = (__half*)(stg + KVTILE);
        __half* sVl = (__half*)(stg + 2 * KVTILE);

        // ---- S = Q K^T (fp16 2-pass) ----
        {
            const int wm  = warp % 4;
            const int wc0 = (warp / 4) * 2;
            nvcuda::wmma::fragment<nvcuda::wmma::accumulator, 16, 16, 16, float> accs[2];
            for (int j = 0; j < 2; j++) nvcuda::wmma::fill_fragment(accs[j], 0.0f);
            for (int ks = 0; ks < HD; ks += 16) {
                nvcuda::wmma::fragment<nvcuda::wmma::matrix_a, 16, 16, 16,
                                       __half, nvcuda::wmma::row_major> fah;
                nvcuda::wmma::fragment<nvcuda::wmma::matrix_a, 16, 16, 16,
                                       __half, nvcuda::wmma::row_major> fal;
                nvcuda::wmma::load_matrix_sync(fah, sQh + (wm * 16) * QLD + ks, QLD);
                nvcuda::wmma::load_matrix_sync(fal, sQl + (wm * 16) * QLD + ks, QLD);
                for (int j = 0; j < 2; j++) {
                    nvcuda::wmma::fragment<nvcuda::wmma::matrix_b, 16, 16, 16,
                                           __half, nvcuda::wmma::col_major> fbh;
                    nvcuda::wmma::load_matrix_sync(fbh, sKh + ((wc0 + j) * 16) * QLD + ks, QLD);
                    nvcuda::wmma::mma_sync(accs[j], fah, fbh, accs[j]);
                    nvcuda::wmma::mma_sync(accs[j], fal, fbh, accs[j]);
                }
            }
            for (int j = 0; j < 2; j++) {
                nvcuda::wmma::store_matrix_sync(sSf + (wm * 16) * SLD + (wc0 + j) * 16,
                                                accs[j], SLD, nvcuda::wmma::mem_row_major);
            }
        }
        __syncthreads();

        // ---- online softmax ----
        {
            const int r  = tid >> 2;
            const int qq = tid & 3;
            const int qg = q0 + r;
            float mold = mrow[r];
            float vals[16];
            float rmax = mold;
#pragma unroll
            for (int j = 0; j < 16; j++) {
                int c = qq + 4 * j;
                float v = sSf[r * SLD + c] * SCALE_F;
                if (k0 + c > qg) v = -1e30f;
                vals[j] = v;
                rmax = fmaxf(rmax, v);
            }
            rmax = fmaxf(rmax, __shfl_xor_sync(0xffffffffu, rmax, 1));
            rmax = fmaxf(rmax, __shfl_xor_sync(0xffffffffu, rmax, 2));
            float alpha = __expf(mold - rmax);
            float rsum = 0.f;
#pragma unroll
            for (int j = 0; j < 16; j++) {
                int c = qq + 4 * j;
                float p = __expf(vals[j] - rmax);
                sPh[r * PLD + c] = __float2half(p);
                rsum += p;
            }
            rsum += __shfl_xor_sync(0xffffffffu, rsum, 1);
            rsum += __shfl_xor_sync(0xffffffffu, rsum, 2);
            if (qq == 0) {
                lrow[r] = lrow[r] * alpha + rsum;
                mrow[r] = rmax;
                arow[r] = alpha;
            }
        }
        __syncthreads();

        // ---- O_delta = P V (fp16 2-pass) ----
        {
            const int wm  = warp % 4;
            const int wn0 = (warp / 4) * 4;
            nvcuda::wmma::fragment<nvcuda::wmma::accumulator, 16, 16, 16, float> accd[4];
            for (int j = 0; j < 4; j++) nvcuda::wmma::fill_fragment(accd[j], 0.0f);
            for (int kc = 0; kc < FBK; kc += 16) {
                nvcuda::wmma::fragment<nvcuda::wmma::matrix_a, 16, 16, 16,
                                       __half, nvcuda::wmma::row_major> pah;
                nvcuda::wmma::load_matrix_sync(pah, sPh + (wm * 16) * PLD + kc, PLD);
                for (int j = 0; j < 4; j++) {
                    nvcuda::wmma::fragment<nvcuda::wmma::matrix_b, 16, 16, 16,
                                           __half, nvcuda::wmma::row_major> vbh;
                    nvcuda::wmma::fragment<nvcuda::wmma::matrix_b, 16, 16, 16,
                                           __half, nvcuda::wmma::row_major> vbl;
                    nvcuda::wmma::load_matrix_sync(vbh, sVh + kc * QLD + (wn0 + j) * 16, QLD);
                    nvcuda::wmma::load_matrix_sync(vbl, sVl + kc * QLD + (wn0 + j) * 16, QLD);
                    nvcuda::wmma::mma_sync(accd[j], pah, vbh, accd[j]);
                    nvcuda::wmma::mma_sync(accd[j], pah, vbl, accd[j]);
                }
            }
            for (int j = 0; j < 4; j++) {
                nvcuda::wmma::store_matrix_sync(sOd + (wm * 16) * 128 + (wn0 + j) * 16,
                                                accd[j], 128, nvcuda::wmma::mem_row_major);
            }
        }
        __syncthreads();

        {
            float alpha = arow[ro];
            const float* od = sOd + ro * 128 + cq * 32;
#pragma unroll
            for (int j = 0; j < 32; j++) o[j] = o[j] * alpha + od[j];
        }
        __syncthreads();
    }

    float inv = 1.0f / lrow[ro];
    size_t yb = ((size_t)(b * T_SEQ) + q0 + ro) * DIM + h * HD + cq * 32;
#pragma unroll
    for (int j = 0; j < 32; j++) {
        float v = o[j] * inv;
        __half hv = __float2half(v);
        Yh[yb + j] = hv;
        Yl[yb + j] = __float2half(v - __half2float(hv));
    }
}

// ---------------- Launch ----------------
extern "C" void kernel_launch(void* const* d_in, const int* in_sizes, int n_in,
                              void* d_out, int out_size)
{
    (void)in_sizes;
    (void)n_in;
    (void)out_size;
    const float* x     = (const float*)d_in[0];
    const float* Wq    = (const float*)d_in[1];
    const float* Wdown = (const float*)d_in[2];
    const float* Wkup  = (const float*)d_in[3];
    const float* Wvup  = (const float*)d_in[4];
    const float* Wproj = (const float*)d_in[5];
    const float* qgain = (const float*)d_in[6];
    float* out = (float*)d_out;

    float* q;
    float* kt;
    cudaGetSymbolAddress((void**)&q,  g_q);
    cudaGetSymbolAddress((void**)&kt, g_kt);

    __half* xhi;
    __half* xlo;
    __half* lhi;
    __half* llo;
    __half* yhi;
    __half* ylo;
    __half* wqd;
    __half* wkv;
    __half* wph;
    cudaGetSymbolAddress((void**)&xhi, g_xhi);
    cudaGetSymbolAddress((void**)&xlo, g_xlo);
    cudaGetSymbolAddress((void**)&lhi, g_lhi);
    cudaGetSymbolAddress((void**)&llo, g_llo);
    cudaGetSymbolAddress((void**)&yhi, g_yhi);
    cudaGetSymbolAddress((void**)&ylo, g_ylo);
    cudaGetSymbolAddress((void**)&wqd, g_wqd);
    cudaGetSymbolAddress((void**)&wkv, g_wkv);
    cudaGetSymbolAddress((void**)&wph, g_wph);

    __half* qah;
    __half* qal;
    __half* kah;
    __half* vth;
    __half* vtl;
    cudaGetSymbolAddress((void**)&qah, g_qah);
    cudaGetSymbolAddress((void**)&qal, g_qal);
    cudaGetSymbolAddress((void**)&kah, g_kah);
    cudaGetSymbolAddress((void**)&vth, g_vth);
    cudaGetSymbolAddress((void**)&vtl, g_vtl);

    cudaFuncSetAttribute(gemm_h, cudaFuncAttributeMaxDynamicSharedMemorySize,
                         GSMEM_BYTES);
    cudaFuncSetAttribute(gemm_h_mix, cudaFuncAttributeMaxDynamicSharedMemorySize,
                         GSMEM_BYTES);
    cudaFuncSetAttribute(flash_mma, cudaFuncAttributeMaxDynamicSharedMemorySize,
                         FA3_SMEM);

    int n1 = NE_MD;
    int n2 = NE_DD;
    int n3 = NE_RD;
    int n4 = NE_RR;
    int nt = T_SEQ * 64;
    rope_table_kernel<<<(nt + 255) / 256, 256>>>();
    split_kernel_h<<<(n1 + 255) / 256, 256>>>(x, xhi, xlo, n1);
    conv_kernel_h<<<(n2 + 255) / 256, 256>>>(Wq, wqd, n2);
    conv_kernel_h<<<(n3 + 255) / 256, 256>>>(Wdown, wqd + NE_DD, n3);
    conv_kernel_h<<<(n4 + 255) / 256, 256>>>(Wkup, wkv, n4);
    conv_kernel_h<<<(n4 + 255) / 256, 256>>>(Wvup, wkv + NE_RR, n4);
    conv_kernel_h<<<(n2 + 255) / 256, 256>>>(Wproj, wph, n2);

    // merged Wq (cols 0..2047 -> fp32 g_q) + Wdown (cols 2048.. -> fp16 lat)
    gemm_h_mix<<<dim3((DIM + RANK) / GBN, M_ROWS / GBM), 256, GSMEM_BYTES>>>(
        xhi, xlo, wqd, q, lhi, llo, M_ROWS, DIM + RANK, DIM, DIM, DIM, RANK);
    // merged Wkup (cols 0..511 -> fp32 g_kt) + Wvup (cols 512.. -> fp16 v)
    gemm_h_mix<<<dim3((2 * RANK) / GBN, M_ROWS / GBM), 256, GSMEM_BYTES>>>(
        lhi, llo, wkv, kt, vth, vtl, M_ROWS, 2 * RANK, RANK, RANK, RANK, RANK);

    rms_rope_kernel<<<dim3(M_ROWS, NHEADS), 128>>>(q, qah, qal, qgain, NHEADS);
    rms_rope_kernel<<<dim3(M_ROWS, NKVH), 128>>>(kt, kah, (__half*)0, (const float*)0, NKVH);

    flash_mma<<<dim3(T_SEQ / FBQ, NHEADS, BATCH), 256, FA3_SMEM>>>(qah, qal, kah,
                                                                   vth, vtl, yhi, ylo);

    gemm_h<<<dim3(DIM / GBN, M_ROWS / GBM), 256, GSMEM_BYTES>>>(
        yhi, ylo, wph, out, M_ROWS, DIM, DIM);
}

// round 16
// speedup vs baseline: 1.1707x; 1.0235x over previous
#include <cuda_runtime.h>
#include <cuda_bf16.h>
#include <cuda_fp16.h>
#include <cuda_pipeline.h>
#include <mma.h>
#include <math.h>

// ---------------- Problem constants ----------------
#define T_SEQ  2048
#define BATCH  2
#define NHEADS 16
#define NKVH   4
#define HD     128
#define DIM    2048
#define RANK   512
#define M_ROWS (BATCH * T_SEQ)
#define EPS_F  1.1920928955078125e-07f
#define SCALE_F 0.08838834764831845f

#define NE_MD (M_ROWS * DIM)
#define NE_MR (M_ROWS * RANK)
#define NE_DD (DIM * DIM)
#define NE_RD (RANK * DIM)
#define NE_RR (RANK * RANK)
#define NE_RT (T_SEQ * 64)

// ---------------- Scratch (static device globals; no allocation) ----------------
__device__ float g_q  [NE_MD];
__device__ float g_kt [NE_MR];

__device__ __half g_xhi[NE_MD];
__device__ __half g_xlo[NE_MD];
__device__ __half g_lhi[NE_MR];
__device__ __half g_llo[NE_MR];
__device__ __half g_yhi[NE_MD];
__device__ __half g_ylo[NE_MD];
__device__ __half g_wqd[NE_DD + NE_RD];   // Wq rows then Wdown rows, [2560 x 2048]
__device__ __half g_wkv[2 * NE_RR];       // Wkup rows then Wvup rows, [1024 x 512]
__device__ __half g_wph[NE_DD];

// flash operands: Q fp16 hi/lo, K fp16, V fp16 hi/lo
__device__ __half g_qah[NE_MD];
__device__ __half g_qal[NE_MD];
__device__ __half g_kah[NE_MR];
__device__ __half g_vth[NE_MR];
__device__ __half g_vtl[NE_MR];

// RoPE table: [T_SEQ][64] -> (cos, sin)
__device__ float2 g_rope[NE_RT];

// ---------------- one mega conversion kernel ----------------
// segments: [0,n1) x->split | [n1,+n2) Wq | [+n3) Wdown | [+n4) Wkup | [+n4) Wvup
//           | [+n2) Wproj | [+NE_RT) rope table
__global__ void prep_kernel(const float* __restrict__ x,
                            const float* __restrict__ Wq,
                            const float* __restrict__ Wdown,
                            const float* __restrict__ Wkup,
                            const float* __restrict__ Wvup,
                            const float* __restrict__ Wproj)
{
    int i = blockIdx.x * blockDim.x + threadIdx.x;
    if (i < NE_MD) {
        float v = x[i];
        __half h = __float2half(v);
        g_xhi[i] = h;
        g_xlo[i] = __float2half(v - __half2float(h));
        return;
    }
    i -= NE_MD;
    if (i < NE_DD) {
        g_wqd[i] = __float2half(Wq[i]);
        return;
    }
    i -= NE_DD;
    if (i < NE_RD) {
        g_wqd[NE_DD + i] = __float2half(Wdown[i]);
        return;
    }
    i -= NE_RD;
    if (i < NE_RR) {
        g_wkv[i] = __float2half(Wkup[i]);
        return;
    }
    i -= NE_RR;
    if (i < NE_RR) {
        g_wkv[NE_RR + i] = __float2half(Wvup[i]);
        return;
    }
    i -= NE_RR;
    if (i < NE_DD) {
        g_wph[i] = __float2half(Wproj[i]);
        return;
    }
    i -= NE_DD;
    if (i < NE_RT) {
        int t = i >> 6;
        int d = i & 63;
        float fr = powf(10000.0f, -(float)d * (1.0f / 64.0f));
        float ang = (float)t * fr;
        float sn, cs;
        sincosf(ang, &sn, &cs);
        g_rope[i] = make_float2(cs, sn);
    }
}
#define PREP_TOTAL (NE_MD + NE_DD + NE_RD + NE_RR + NE_RR + NE_DD + NE_RT)

// ---------------- WMMA fp16x2 GEMM, cp.async 2-stage, BK=64 ----------------
#define GBM 128
#define GBN 128
#define GBK 64
#define GLDS 72
#define GTILE (GBM * GLDS)
#define GSTG (3 * GTILE)
#define GSMEM_BYTES (2 * GSTG * 2)          // 110592

__device__ __forceinline__ void gemm_stage_load_h(
    __half* s,
    const __half* Ah, const __half* Al, const __half* Bh,
    int bm, int bn, int K, int k0, int tid)
{
    __half* sAh = s;
    __half* sAl = s + GTILE;
    __half* sBh = s + 2 * GTILE;
    for (int i = 0; i < 4; i++) {
        int idx = tid + 256 * i;
        int row = idx >> 3;
        int c8  = (idx & 7) * 8;
        __pipeline_memcpy_async(sAh + row * GLDS + c8,
                                Ah + (size_t)(bm + row) * K + k0 + c8, 16);
        __pipeline_memcpy_async(sAl + row * GLDS + c8,
                                Al + (size_t)(bm + row) * K + k0 + c8, 16);
        __pipeline_memcpy_async(sBh + row * GLDS + c8,
                                Bh + (size_t)(bn + row) * K + k0 + c8, 16);
    }
}

// plain GEMM, fp32 output (Wproj)
__global__ __launch_bounds__(256) void gemm_h(
    const __half* __restrict__ Ah, const __half* __restrict__ Al,
    const __half* __restrict__ Bh,
    float* __restrict__ C, int M, int N, int K)
{
    extern __shared__ __half gsm[];

    const int tid  = threadIdx.x;
    const int warp = tid / 32;
    const int wm   = (warp % 2) * 64;
    const int wn   = (warp / 2) * 32;
    const int bm   = blockIdx.y * GBM;
    const int bn   = blockIdx.x * GBN;

    nvcuda::wmma::fragment<nvcuda::wmma::accumulator, 16, 16, 16, float> acc[4][2];
    for (int i = 0; i < 4; i++) {
        for (int j = 0; j < 2; j++) {
            nvcuda::wmma::fill_fragment(acc[i][j], 0.0f);
        }
    }

    const int nk = K / GBK;

    gemm_stage_load_h(gsm, Ah, Al, Bh, bm, bn, K, 0, tid);
    __pipeline_commit();

    for (int it = 0; it < nk; it++) {
        if (it + 1 < nk) {
            gemm_stage_load_h(gsm + ((it + 1) & 1) * GSTG, Ah, Al, Bh, bm, bn, K,
                              (it + 1) * GBK, tid);
            __pipeline_commit();
            __pipeline_wait_prior(1);
        } else {
            __pipeline_wait_prior(0);
        }
        __syncthreads();

        __half* sAh = gsm + (it & 1) * GSTG;
        __half* sAl = sAh + GTILE;
        __half* sBh = sAh + 2 * GTILE;

        for (int ks = 0; ks < GBK; ks += 16) {
            nvcuda::wmma::fragment<nvcuda::wmma::matrix_a, 16, 16, 16,
                                   __half, nvcuda::wmma::row_major> fah[4];
            nvcuda::wmma::fragment<nvcuda::wmma::matrix_a, 16, 16, 16,
                                   __half, nvcuda::wmma::row_major> fal[4];
            nvcuda::wmma::fragment<nvcuda::wmma::matrix_b, 16, 16, 16,
                                   __half, nvcuda::wmma::col_major> fbh[2];
            for (int i = 0; i < 4; i++) {
                nvcuda::wmma::load_matrix_sync(fah[i], sAh + (wm + i * 16) * GLDS + ks, GLDS);
                nvcuda::wmma::load_matrix_sync(fal[i], sAl + (wm + i * 16) * GLDS + ks, GLDS);
            }
            for (int j = 0; j < 2; j++) {
                nvcuda::wmma::load_matrix_sync(fbh[j], sBh + (wn + j * 16) * GLDS + ks, GLDS);
            }
            for (int i = 0; i < 4; i++) {
                for (int j = 0; j < 2; j++) {
                    nvcuda::wmma::mma_sync(acc[i][j], fah[i], fbh[j], acc[i][j]);
                    nvcuda::wmma::mma_sync(acc[i][j], fal[i], fbh[j], acc[i][j]);
                }
            }
        }
        __syncthreads();
    }

    for (int i = 0; i < 4; i++) {
        for (int j = 0; j < 2; j++) {
            float* cp = C + (size_t)(bm + wm + i * 16) * N + bn + wn + j * 16;
            nvcuda::wmma::store_matrix_sync(cp, acc[i][j], N, nvcuda::wmma::mem_row_major);
        }
    }
}

// Merged GEMM: column blocks below Nsplit -> fp32 (ld ldf); at/above -> fp16 hi/lo.
__global__ __launch_bounds__(256) void gemm_h_mix(
    const __half* __restrict__ Ah, const __half* __restrict__ Al,
    const __half* __restrict__ Bh,
    float* __restrict__ Cf, __half* __restrict__ Chi, __half* __restrict__ Clo,
    int M, int N, int K, int Nsplit, int ldf, int ldh)
{
    extern __shared__ __half gsm[];

    const int tid  = threadIdx.x;
    const int warp = tid / 32;
    const int wm   = (warp % 2) * 64;
    const int wn   = (warp / 2) * 32;
    const int bm   = blockIdx.y * GBM;
    const int bn   = blockIdx.x * GBN;

    nvcuda::wmma::fragment<nvcuda::wmma::accumulator, 16, 16, 16, float> acc[4][2];
    for (int i = 0; i < 4; i++) {
        for (int j = 0; j < 2; j++) {
            nvcuda::wmma::fill_fragment(acc[i][j], 0.0f);
        }
    }

    const int nk = K / GBK;

    gemm_stage_load_h(gsm, Ah, Al, Bh, bm, bn, K, 0, tid);
    __pipeline_commit();

    for (int it = 0; it < nk; it++) {
        if (it + 1 < nk) {
            gemm_stage_load_h(gsm + ((it + 1) & 1) * GSTG, Ah, Al, Bh, bm, bn, K,
                              (it + 1) * GBK, tid);
            __pipeline_commit();
            __pipeline_wait_prior(1);
        } else {
            __pipeline_wait_prior(0);
        }
        __syncthreads();

        __half* sAh = gsm + (it & 1) * GSTG;
        __half* sAl = sAh + GTILE;
        __half* sBh = sAh + 2 * GTILE;

        for (int ks = 0; ks < GBK; ks += 16) {
            nvcuda::wmma::fragment<nvcuda::wmma::matrix_a, 16, 16, 16,
                                   __half, nvcuda::wmma::row_major> fah[4];
            nvcuda::wmma::fragment<nvcuda::wmma::matrix_a, 16, 16, 16,
                                   __half, nvcuda::wmma::row_major> fal[4];
            nvcuda::wmma::fragment<nvcuda::wmma::matrix_b, 16, 16, 16,
                                   __half, nvcuda::wmma::col_major> fbh[2];
            for (int i = 0; i < 4; i++) {
                nvcuda::wmma::load_matrix_sync(fah[i], sAh + (wm + i * 16) * GLDS + ks, GLDS);
                nvcuda::wmma::load_matrix_sync(fal[i], sAl + (wm + i * 16) * GLDS + ks, GLDS);
            }
            for (int j = 0; j < 2; j++) {
                nvcuda::wmma::load_matrix_sync(fbh[j], sBh + (wn + j * 16) * GLDS + ks, GLDS);
            }
            for (int i = 0; i < 4; i++) {
                for (int j = 0; j < 2; j++) {
                    nvcuda::wmma::mma_sync(acc[i][j], fah[i], fbh[j], acc[i][j]);
                    nvcuda::wmma::mma_sync(acc[i][j], fal[i], fbh[j], acc[i][j]);
                }
            }
        }
        __syncthreads();
    }

    if (bn < Nsplit) {
        for (int i = 0; i < 4; i++) {
            for (int j = 0; j < 2; j++) {
                float* cp = Cf + (size_t)(bm + wm + i * 16) * ldf + bn + wn + j * 16;
                nvcuda::wmma::store_matrix_sync(cp, acc[i][j], ldf,
                                                nvcuda::wmma::mem_row_major);
            }
        }
    } else {
        float* stage = (float*)gsm;
        for (int i = 0; i < 4; i++) {
            for (int j = 0; j < 2; j++) {
                nvcuda::wmma::store_matrix_sync(stage + (wm + i * 16) * 128 + wn + j * 16,
                                                acc[i][j], 128, nvcuda::wmma::mem_row_major);
            }
        }
        __syncthreads();
        int cb = bn - Nsplit;
        for (int t = tid; t < GBM * GBN; t += 256) {
            int r = t >> 7;
            int c = t & 127;
            float v = stage[t];
            __half hv = __float2half(v);
            size_t gi = (size_t)(bm + r) * ldh + cb + c;
            Chi[gi] = hv;
            Clo[gi] = __float2half(v - __half2float(hv));
        }
    }
}

// ---------------- RMSNorm + RoPE merged q+k, table-driven ----------------
// blockIdx.y < NHEADS: q path (src g_q ld DIM, out qah/qal, gain)
// else: k path (head = y-NHEADS, src g_kt ld RANK, out kah only)
__global__ void rms_rope_kernel(const float* __restrict__ gain)
{
    const int m = blockIdx.x;
    const int hy = blockIdx.y;
    const int d = threadIdx.x;
    const int b = m / T_SEQ;
    const int t = m % T_SEQ;

    const int isq = (hy < NHEADS) ? 1 : 0;
    const int h = isq ? hy : (hy - NHEADS);
    const float* src = isq ? (g_q + (size_t)m * DIM + h * HD)
                           : (g_kt + (size_t)m * RANK + h * HD);

    float x = src[d];
    float ss = x * x;
#pragma unroll
    for (int o = 16; o > 0; o >>= 1) ss += __shfl_xor_sync(0xffffffffu, ss, o);
    __shared__ float red[4];
    __shared__ float sv[HD];
    if ((d & 31) == 0) red[d >> 5] = ss;
    __syncthreads();
    float tot = red[0] + red[1] + red[2] + red[3];
    float r = rsqrtf(tot * (1.0f / HD) + EPS_F);
    sv[d] = x * r;
    __syncthreads();
    if (d < 64) {
        float x1 = sv[d];
        float x2 = sv[d + 64];
        float2 cs2 = g_rope[(size_t)t * 64 + d];
        if (isq) {
            float g = gain[h];
            float v1 = (x1 * cs2.x + x2 * cs2.y) * g;
            float v2 = (x2 * cs2.x - x1 * cs2.y) * g;
            size_t base = ((size_t)(b * NHEADS + h) * T_SEQ + t) * HD;
            __half h1 = __float2half(v1);
            __half h2 = __float2half(v2);
            g_qah[base + d]      = h1;
            g_qah[base + 64 + d] = h2;
            g_qal[base + d]      = __float2half(v1 - __half2float(h1));
            g_qal[base + 64 + d] = __float2half(v2 - __half2float(h2));
        } else {
            float v1 = x1 * cs2.x + x2 * cs2.y;
            float v2 = x2 * cs2.x - x1 * cs2.y;
            size_t base = ((size_t)(b * NKVH + h) * T_SEQ + t) * HD;
            g_kah[base + d]      = __float2half(v1);
            g_kah[base + 64 + d] = __float2half(v2);
        }
    }
}

// ---------------- Flash attention (all fp16 2-pass, fp32 softmax) ----------------
#define FBQ 64
#define FBK 64
#define QLD 136
#define PLD 72
#define SLD 68

#define OQH 0
#define OQL (OQH + FBQ * QLD * 2)
#define OKV (OQL + FBQ * QLD * 2)
#define KVTILE (FBK * QLD * 2)
#define KVSTG (3 * KVTILE)
#define OPH (OKV + 2 * KVSTG)
#define OSF (OPH + FBQ * PLD * 2)
#define OMR (OSF + FBQ * 128 * 4)
#define OLR (OMR + 256)
#define OAR (OLR + 256)
#define FA3_SMEM (OAR + 256)

__device__ __forceinline__ void fa_stage_load(
    char* smb, int s,
    const __half* ksh, const __half* vsh, const __half* vsl, int tid)
{
    char* st = smb + OKV + s * KVSTG;
    __half* sKh = (__half*)st;
    __half* sVh = (__half*)(st + KVTILE);
    __half* sVl = (__half*)(st + 2 * KVTILE);
    for (int i = 0; i < 4; i++) {
        int idx = tid + 256 * i;
        int r = idx >> 4;
        int c = (idx & 15) * 8;
        __pipeline_memcpy_async(sKh + r * QLD + c, ksh + (size_t)r * HD + c, 16);
        __pipeline_memcpy_async(sVh + r * QLD + c, vsh + (size_t)r * RANK + c, 16);
        __pipeline_memcpy_async(sVl + r * QLD + c, vsl + (size_t)r * RANK + c, 16);
    }
}

__global__ __launch_bounds__(256) void flash_mma(
    const __half* __restrict__ Qhi, const __half* __restrict__ Qlo,
    const __half* __restrict__ Khi,
    const __half* __restrict__ Vhi, const __half* __restrict__ Vlo,
    __half* __restrict__ Yh, __half* __restrict__ Yl)
{
    extern __shared__ char smb[];
    __half* sQh = (__half*)(smb + OQH);
    __half* sQl = (__half*)(smb + OQL);
    __half* sPh = (__half*)(smb + OPH);
    float* sSf  = (float*)(smb + OSF);
    float* sOd  = (float*)(smb + OSF);
    float* mrow = (float*)(smb + OMR);
    float* lrow = (float*)(smb + OLR);
    float* arow = (float*)(smb + OAR);

    const int tid  = threadIdx.x;
    const int warp = tid / 32;
    const int qt = (int)(gridDim.x - 1 - blockIdx.x);
    const int h  = blockIdx.y;
    const int b  = blockIdx.z;
    const int kh = h >> 2;
    const int q0 = qt * FBQ;

    const __half* Kh0 = Khi + ((size_t)(b * NKVH + kh) * T_SEQ) * HD;
    const __half* Vh0 = Vhi + (size_t)b * T_SEQ * RANK + kh * HD;
    const __half* Vl0 = Vlo + (size_t)b * T_SEQ * RANK + kh * HD;

    const __half* qsh = Qhi + ((size_t)(b * NHEADS + h) * T_SEQ + q0) * HD;
    const __half* qsl = Qlo + ((size_t)(b * NHEADS + h) * T_SEQ + q0) * HD;
    for (int i = tid; i < FBQ * HD / 8; i += 256) {
        int r = i >> 4;
        int c = (i & 15) * 8;
        *(uint4*)(sQh + r * QLD + c) = *(const uint4*)(qsh + (size_t)r * HD + c);
        *(uint4*)(sQl + r * QLD + c) = *(const uint4*)(qsl + (size_t)r * HD + c);
    }
    if (tid < 64) {
        mrow[tid] = -1e30f;
        lrow[tid] = 0.f;
    }

    float o[32];
#pragma unroll
    for (int j = 0; j < 32; j++) o[j] = 0.f;

    const int ro = tid >> 2;
    const int cq = tid & 3;

    fa_stage_load(smb, 0, Kh0, Vh0, Vl0, tid);
    __pipeline_commit();
    __syncthreads();

    for (int kt = 0; kt <= qt; kt++) {
        const int k0 = kt * FBK;
        if (kt < qt) {
            int k1 = (kt + 1) * FBK;
            fa_stage_load(smb, (kt + 1) & 1,
                          Kh0 + (size_t)k1 * HD,
                          Vh0 + (size_t)k1 * RANK, Vl0 + (size_t)k1 * RANK, tid);
            __pipeline_commit();
            __pipeline_wait_prior(1);
        } else {
            __pipeline_wait_prior(0);
        }
        __syncthreads();

        char* stg = smb + OKV + (size_t)(kt & 1) * KVSTG;
        __half* sKh = (__half*)stg;
        __half* sVh = (__half*)(stg + KVTILE);
        __half* sVl = (__half*)(stg + 2 * KVTILE);

        // ---- S = Q K^T (fp16 2-pass) ----
        {
            const int wm  = warp % 4;
            const int wc0 = (warp / 4) * 2;
            nvcuda::wmma::fragment<nvcuda::wmma::accumulator, 16, 16, 16, float> accs[2];
            for (int j = 0; j < 2; j++) nvcuda::wmma::fill_fragment(accs[j], 0.0f);
            for (int ks = 0; ks < HD; ks += 16) {
                nvcuda::wmma::fragment<nvcuda::wmma::matrix_a, 16, 16, 16,
                                       __half, nvcuda::wmma::row_major> fah;
                nvcuda::wmma::fragment<nvcuda::wmma::matrix_a, 16, 16, 16,
                                       __half, nvcuda::wmma::row_major> fal;
                nvcuda::wmma::load_matrix_sync(fah, sQh + (wm * 16) * QLD + ks, QLD);
                nvcuda::wmma::load_matrix_sync(fal, sQl + (wm * 16) * QLD + ks, QLD);
                for (int j = 0; j < 2; j++) {
                    nvcuda::wmma::fragment<nvcuda::wmma::matrix_b, 16, 16, 16,
                                           __half, nvcuda::wmma::col_major> fbh;
                    nvcuda::wmma::load_matrix_sync(fbh, sKh + ((wc0 + j) * 16) * QLD + ks, QLD);
                    nvcuda::wmma::mma_sync(accs[j], fah, fbh, accs[j]);
                    nvcuda::wmma::mma_sync(accs[j], fal, fbh, accs[j]);
                }
            }
            for (int j = 0; j < 2; j++) {
                nvcuda::wmma::store_matrix_sync(sSf + (wm * 16) * SLD + (wc0 + j) * 16,
                                                accs[j], SLD, nvcuda::wmma::mem_row_major);
            }
        }
        __syncthreads();

        // ---- online softmax ----
        {
            const int r  = tid >> 2;
            const int qq = tid & 3;
            const int qg = q0 + r;
            float mold = mrow[r];
            float vals[16];
            float rmax = mold;
#pragma unroll
            for (int j = 0; j < 16; j++) {
                int c = qq + 4 * j;
                float v = sSf[r * SLD + c] * SCALE_F;
                if (k0 + c > qg) v = -1e30f;
                vals[j] = v;
                rmax = fmaxf(rmax, v);
            }
            rmax = fmaxf(rmax, __shfl_xor_sync(0xffffffffu, rmax, 1));
            rmax = fmaxf(rmax, __shfl_xor_sync(0xffffffffu, rmax, 2));
            float alpha = __expf(mold - rmax);
            float rsum = 0.f;
#pragma unroll
            for (int j = 0; j < 16; j++) {
                int c = qq + 4 * j;
                float p = __expf(vals[j] - rmax);
                sPh[r * PLD + c] = __float2half(p);
                rsum += p;
            }
            rsum += __shfl_xor_sync(0xffffffffu, rsum, 1);
            rsum += __shfl_xor_sync(0xffffffffu, rsum, 2);
            if (qq == 0) {
                lrow[r] = lrow[r] * alpha + rsum;
                mrow[r] = rmax;
                arow[r] = alpha;
            }
        }
        __syncthreads();

        // ---- O_delta = P V (fp16 2-pass, warp tile 32x32) ----
        {
            const int wmP = (warp & 1) * 32;        // row base
            const int wnP = (warp >> 1) * 32;       // col base
            nvcuda::wmma::fragment<nvcuda::wmma::accumulator, 16, 16, 16, float> accd[2][2];
            for (int i = 0; i < 2; i++)
                for (int j = 0; j < 2; j++)
                    nvcuda::wmma::fill_fragment(accd[i][j], 0.0f);
            for (int kc = 0; kc < FBK; kc += 16) {
                nvcuda::wmma::fragment<nvcuda::wmma::matrix_a, 16, 16, 16,
                                       __half, nvcuda::wmma::row_major> pah[2];
                for (int i = 0; i < 2; i++) {
                    nvcuda::wmma::load_matrix_sync(pah[i],
                        sPh + (wmP + i * 16) * PLD + kc, PLD);
                }
                for (int j = 0; j < 2; j++) {
                    nvcuda::wmma::fragment<nvcuda::wmma::matrix_b, 16, 16, 16,
                                           __half, nvcuda::wmma::row_major> vbh;
                    nvcuda::wmma::fragment<nvcuda::wmma::matrix_b, 16, 16, 16,
                                           __half, nvcuda::wmma::row_major> vbl;
                    nvcuda::wmma::load_matrix_sync(vbh, sVh + kc * QLD + wnP + j * 16, QLD);
                    nvcuda::wmma::load_matrix_sync(vbl, sVl + kc * QLD + wnP + j * 16, QLD);
                    for (int i = 0; i < 2; i++) {
                        nvcuda::wmma::mma_sync(accd[i][j], pah[i], vbh, accd[i][j]);
                        nvcuda::wmma::mma_sync(accd[i][j], pah[i], vbl, accd[i][j]);
                    }
                }
            }
            for (int i = 0; i < 2; i++) {
                for (int j = 0; j < 2; j++) {
                    nvcuda::wmma::store_matrix_sync(
                        sOd + (wmP + i * 16) * 128 + wnP + j * 16,
                        accd[i][j], 128, nvcuda::wmma::mem_row_major);
                }
            }
        }
        __syncthreads();

        {
            float alpha = arow[ro];
            const float* od = sOd + ro * 128 + cq * 32;
#pragma unroll
            for (int j = 0; j < 32; j++) o[j] = o[j] * alpha + od[j];
        }
        __syncthreads();
    }

    float inv = 1.0f / lrow[ro];
    size_t yb = ((size_t)(b * T_SEQ) + q0 + ro) * DIM + h * HD + cq * 32;
#pragma unroll
    for (int j = 0; j < 32; j++) {
        float v = o[j] * inv;
        __half hv = __float2half(v);
        Yh[yb + j] = hv;
        Yl[yb + j] = __float2half(v - __half2float(hv));
    }
}

// ---------------- Launch ----------------
extern "C" void kernel_launch(void* const* d_in, const int* in_sizes, int n_in,
                              void* d_out, int out_size)
{
    (void)in_sizes;
    (void)n_in;
    (void)out_size;
    const float* x     = (const float*)d_in[0];
    const float* Wq    = (const float*)d_in[1];
    const float* Wdown = (const float*)d_in[2];
    const float* Wkup  = (const float*)d_in[3];
    const float* Wvup  = (const float*)d_in[4];
    const float* Wproj = (const float*)d_in[5];
    const float* qgain = (const float*)d_in[6];
    float* out = (float*)d_out;

    float* q;
    float* kt;
    cudaGetSymbolAddress((void**)&q,  g_q);
    cudaGetSymbolAddress((void**)&kt, g_kt);

    __half* xhi;
    __half* xlo;
    __half* lhi;
    __half* llo;
    __half* yhi;
    __half* ylo;
    __half* wqd;
    __half* wkv;
    __half* wph;
    cudaGetSymbolAddress((void**)&xhi, g_xhi);
    cudaGetSymbolAddress((void**)&xlo, g_xlo);
    cudaGetSymbolAddress((void**)&lhi, g_lhi);
    cudaGetSymbolAddress((void**)&llo, g_llo);
    cudaGetSymbolAddress((void**)&yhi, g_yhi);
    cudaGetSymbolAddress((void**)&ylo, g_ylo);
    cudaGetSymbolAddress((void**)&wqd, g_wqd);
    cudaGetSymbolAddress((void**)&wkv, g_wkv);
    cudaGetSymbolAddress((void**)&wph, g_wph);

    __half* qah;
    __half* qal;
    __half* kah;
    __half* vth;
    __half* vtl;
    cudaGetSymbolAddress((void**)&qah, g_qah);
    cudaGetSymbolAddress((void**)&qal, g_qal);
    cudaGetSymbolAddress((void**)&kah, g_kah);
    cudaGetSymbolAddress((void**)&vth, g_vth);
    cudaGetSymbolAddress((void**)&vtl, g_vtl);

    cudaFuncSetAttribute(gemm_h, cudaFuncAttributeMaxDynamicSharedMemorySize,
                         GSMEM_BYTES);
    cudaFuncSetAttribute(gemm_h_mix, cudaFuncAttributeMaxDynamicSharedMemorySize,
                         GSMEM_BYTES);
    cudaFuncSetAttribute(flash_mma, cudaFuncAttributeMaxDynamicSharedMemorySize,
                         FA3_SMEM);

    long long ptot = PREP_TOTAL;
    prep_kernel<<<(int)((ptot + 255) / 256), 256>>>(x, Wq, Wdown, Wkup, Wvup, Wproj);

    // merged Wq (cols 0..2047 -> fp32 g_q) + Wdown (cols 2048.. -> fp16 lat)
    gemm_h_mix<<<dim3((DIM + RANK) / GBN, M_ROWS / GBM), 256, GSMEM_BYTES>>>(
        xhi, xlo, wqd, q, lhi, llo, M_ROWS, DIM + RANK, DIM, DIM, DIM, RANK);
    // merged Wkup (cols 0..511 -> fp32 g_kt) + Wvup (cols 512.. -> fp16 v)
    gemm_h_mix<<<dim3((2 * RANK) / GBN, M_ROWS / GBM), 256, GSMEM_BYTES>>>(
        lhi, llo, wkv, kt, vth, vtl, M_ROWS, 2 * RANK, RANK, RANK, RANK, RANK);

    rms_rope_kernel<<<dim3(M_ROWS, NHEADS + NKVH), 128>>>(qgain);

    flash_mma<<<dim3(T_SEQ / FBQ, NHEADS, BATCH), 256, FA3_SMEM>>>(qah, qal, kah,
                                                                   vth, vtl, yhi, ylo);

    gemm_h<<<dim3(DIM / GBN, M_ROWS / GBM), 256, GSMEM_BYTES>>>(
        yhi, ylo, wph, out, M_ROWS, DIM, DIM);
}

// round 17
// speedup vs baseline: 1.1938x; 1.0198x over previous
#include <cuda_runtime.h>
#include <cuda_bf16.h>
#include <cuda_fp16.h>
#include <cuda_pipeline.h>
#include <mma.h>
#include <math.h>

// ---------------- Problem constants ----------------
#define T_SEQ  2048
#define BATCH  2
#define NHEADS 16
#define NKVH   4
#define HD     128
#define DIM    2048
#define RANK   512
#define M_ROWS (BATCH * T_SEQ)
#define EPS_F  1.1920928955078125e-07f
#define SCALE_F 0.08838834764831845f

#define NE_MD (M_ROWS * DIM)
#define NE_MR (M_ROWS * RANK)
#define NE_DD (DIM * DIM)
#define NE_RD (RANK * DIM)
#define NE_RR (RANK * RANK)
#define NE_RT (T_SEQ * 64)

// ---------------- Scratch (static device globals; no allocation) ----------------
__device__ float g_q  [NE_MD];
__device__ float g_kt [NE_MR];

__device__ __half g_xhi[NE_MD];
__device__ __half g_xlo[NE_MD];
__device__ __half g_lhi[NE_MR];
__device__ __half g_llo[NE_MR];
__device__ __half g_yhi[NE_MD];
__device__ __half g_ylo[NE_MD];
__device__ __half g_wqd[NE_DD + NE_RD];
__device__ __half g_wkv[2 * NE_RR];
__device__ __half g_wph[NE_DD];

__device__ __half g_qah[NE_MD];
__device__ __half g_qal[NE_MD];
__device__ __half g_kah[NE_MR];
__device__ __half g_vth[NE_MR];
__device__ __half g_vtl[NE_MR];

__device__ float2 g_rope[NE_RT];

// ---------------- one mega conversion kernel ----------------
__global__ void prep_kernel(const float* __restrict__ x,
                            const float* __restrict__ Wq,
                            const float* __restrict__ Wdown,
                            const float* __restrict__ Wkup,
                            const float* __restrict__ Wvup,
                            const float* __restrict__ Wproj)
{
    int i = blockIdx.x * blockDim.x + threadIdx.x;
    if (i < NE_MD) {
        float v = x[i];
        __half h = __float2half(v);
        g_xhi[i] = h;
        g_xlo[i] = __float2half(v - __half2float(h));
        return;
    }
    i -= NE_MD;
    if (i < NE_DD) {
        g_wqd[i] = __float2half(Wq[i]);
        return;
    }
    i -= NE_DD;
    if (i < NE_RD) {
        g_wqd[NE_DD + i] = __float2half(Wdown[i]);
        return;
    }
    i -= NE_RD;
    if (i < NE_RR) {
        g_wkv[i] = __float2half(Wkup[i]);
        return;
    }
    i -= NE_RR;
    if (i < NE_RR) {
        g_wkv[NE_RR + i] = __float2half(Wvup[i]);
        return;
    }
    i -= NE_RR;
    if (i < NE_DD) {
        g_wph[i] = __float2half(Wproj[i]);
        return;
    }
    i -= NE_DD;
    if (i < NE_RT) {
        int t = i >> 6;
        int d = i & 63;
        float fr = powf(10000.0f, -(float)d * (1.0f / 64.0f));
        float ang = (float)t * fr;
        float sn, cs;
        sincosf(ang, &sn, &cs);
        g_rope[i] = make_float2(cs, sn);
    }
}
#define PREP_TOTAL (NE_MD + NE_DD + NE_RD + NE_RR + NE_RR + NE_DD + NE_RT)

// ---------------- WMMA fp16x2 GEMM, cp.async 2-stage, BK=64 ----------------
#define GBM 128
#define GBN 128
#define GBK 64
#define GLDS 72
#define GTILE (GBM * GLDS)
#define GSTG (3 * GTILE)
#define GSMEM_BYTES (2 * GSTG * 2)          // 110592

__device__ __forceinline__ void gemm_stage_load_h(
    __half* s,
    const __half* Ah, const __half* Al, const __half* Bh,
    int bm, int bn, int K, int k0, int tid)
{
    __half* sAh = s;
    __half* sAl = s + GTILE;
    __half* sBh = s + 2 * GTILE;
    for (int i = 0; i < 4; i++) {
        int idx = tid + 256 * i;
        int row = idx >> 3;
        int c8  = (idx & 7) * 8;
        __pipeline_memcpy_async(sAh + row * GLDS + c8,
                                Ah + (size_t)(bm + row) * K + k0 + c8, 16);
        __pipeline_memcpy_async(sAl + row * GLDS + c8,
                                Al + (size_t)(bm + row) * K + k0 + c8, 16);
        __pipeline_memcpy_async(sBh + row * GLDS + c8,
                                Bh + (size_t)(bn + row) * K + k0 + c8, 16);
    }
}

__global__ __launch_bounds__(256) void gemm_h(
    const __half* __restrict__ Ah, const __half* __restrict__ Al,
    const __half* __restrict__ Bh,
    float* __restrict__ C, int M, int N, int K)
{
    extern __shared__ __half gsm[];

    const int tid  = threadIdx.x;
    const int warp = tid / 32;
    const int wm   = (warp % 2) * 64;
    const int wn   = (warp / 2) * 32;
    const int bm   = blockIdx.y * GBM;
    const int bn   = blockIdx.x * GBN;

    nvcuda::wmma::fragment<nvcuda::wmma::accumulator, 16, 16, 16, float> acc[4][2];
    for (int i = 0; i < 4; i++) {
        for (int j = 0; j < 2; j++) {
            nvcuda::wmma::fill_fragment(acc[i][j], 0.0f);
        }
    }

    const int nk = K / GBK;

    gemm_stage_load_h(gsm, Ah, Al, Bh, bm, bn, K, 0, tid);
    __pipeline_commit();

    for (int it = 0; it < nk; it++) {
        if (it + 1 < nk) {
            gemm_stage_load_h(gsm + ((it + 1) & 1) * GSTG, Ah, Al, Bh, bm, bn, K,
                              (it + 1) * GBK, tid);
            __pipeline_commit();
            __pipeline_wait_prior(1);
        } else {
            __pipeline_wait_prior(0);
        }
        __syncthreads();

        __half* sAh = gsm + (it & 1) * GSTG;
        __half* sAl = sAh + GTILE;
        __half* sBh = sAh + 2 * GTILE;

        for (int ks = 0; ks < GBK; ks += 16) {
            nvcuda::wmma::fragment<nvcuda::wmma::matrix_a, 16, 16, 16,
                                   __half, nvcuda::wmma::row_major> fah[4];
            nvcuda::wmma::fragment<nvcuda::wmma::matrix_a, 16, 16, 16,
                                   __half, nvcuda::wmma::row_major> fal[4];
            nvcuda::wmma::fragment<nvcuda::wmma::matrix_b, 16, 16, 16,
                                   __half, nvcuda::wmma::col_major> fbh[2];
            for (int i = 0; i < 4; i++) {
                nvcuda::wmma::load_matrix_sync(fah[i], sAh + (wm + i * 16) * GLDS + ks, GLDS);
                nvcuda::wmma::load_matrix_sync(fal[i], sAl + (wm + i * 16) * GLDS + ks, GLDS);
            }
            for (int j = 0; j < 2; j++) {
                nvcuda::wmma::load_matrix_sync(fbh[j], sBh + (wn + j * 16) * GLDS + ks, GLDS);
            }
            for (int i = 0; i < 4; i++) {
                for (int j = 0; j < 2; j++) {
                    nvcuda::wmma::mma_sync(acc[i][j], fah[i], fbh[j], acc[i][j]);
                    nvcuda::wmma::mma_sync(acc[i][j], fal[i], fbh[j], acc[i][j]);
                }
            }
        }
        __syncthreads();
    }

    for (int i = 0; i < 4; i++) {
        for (int j = 0; j < 2; j++) {
            float* cp = C + (size_t)(bm + wm + i * 16) * N + bn + wn + j * 16;
            nvcuda::wmma::store_matrix_sync(cp, acc[i][j], N, nvcuda::wmma::mem_row_major);
        }
    }
}

// Merged GEMM: column blocks below Nsplit -> fp32; at/above -> fp16 hi/lo.
__global__ __launch_bounds__(256) void gemm_h_mix(
    const __half* __restrict__ Ah, const __half* __restrict__ Al,
    const __half* __restrict__ Bh,
    float* __restrict__ Cf, __half* __restrict__ Chi, __half* __restrict__ Clo,
    int M, int N, int K, int Nsplit, int ldf, int ldh)
{
    extern __shared__ __half gsm[];

    const int tid  = threadIdx.x;
    const int warp = tid / 32;
    const int wm   = (warp % 2) * 64;
    const int wn   = (warp / 2) * 32;
    const int bm   = blockIdx.y * GBM;
    const int bn   = blockIdx.x * GBN;

    nvcuda::wmma::fragment<nvcuda::wmma::accumulator, 16, 16, 16, float> acc[4][2];
    for (int i = 0; i < 4; i++) {
        for (int j = 0; j < 2; j++) {
            nvcuda::wmma::fill_fragment(acc[i][j], 0.0f);
        }
    }

    const int nk = K / GBK;

    gemm_stage_load_h(gsm, Ah, Al, Bh, bm, bn, K, 0, tid);
    __pipeline_commit();

    for (int it = 0; it < nk; it++) {
        if (it + 1 < nk) {
            gemm_stage_load_h(gsm + ((it + 1) & 1) * GSTG, Ah, Al, Bh, bm, bn, K,
                              (it + 1) * GBK, tid);
            __pipeline_commit();
            __pipeline_wait_prior(1);
        } else {
            __pipeline_wait_prior(0);
        }
        __syncthreads();

        __half* sAh = gsm + (it & 1) * GSTG;
        __half* sAl = sAh + GTILE;
        __half* sBh = sAh + 2 * GTILE;

        for (int ks = 0; ks < GBK; ks += 16) {
            nvcuda::wmma::fragment<nvcuda::wmma::matrix_a, 16, 16, 16,
                                   __half, nvcuda::wmma::row_major> fah[4];
            nvcuda::wmma::fragment<nvcuda::wmma::matrix_a, 16, 16, 16,
                                   __half, nvcuda::wmma::row_major> fal[4];
            nvcuda::wmma::fragment<nvcuda::wmma::matrix_b, 16, 16, 16,
                                   __half, nvcuda::wmma::col_major> fbh[2];
            for (int i = 0; i < 4; i++) {
                nvcuda::wmma::load_matrix_sync(fah[i], sAh + (wm + i * 16) * GLDS + ks, GLDS);
                nvcuda::wmma::load_matrix_sync(fal[i], sAl + (wm + i * 16) * GLDS + ks, GLDS);
            }
            for (int j = 0; j < 2; j++) {
                nvcuda::wmma::load_matrix_sync(fbh[j], sBh + (wn + j * 16) * GLDS + ks, GLDS);
            }
            for (int i = 0; i < 4; i++) {
                for (int j = 0; j < 2; j++) {
                    nvcuda::wmma::mma_sync(acc[i][j], fah[i], fbh[j], acc[i][j]);
                    nvcuda::wmma::mma_sync(acc[i][j], fal[i], fbh[j], acc[i][j]);
                }
            }
        }
        __syncthreads();
    }

    if (bn < Nsplit) {
        for (int i = 0; i < 4; i++) {
            for (int j = 0; j < 2; j++) {
                float* cp = Cf + (size_t)(bm + wm + i * 16) * ldf + bn + wn + j * 16;
                nvcuda::wmma::store_matrix_sync(cp, acc[i][j], ldf,
                                                nvcuda::wmma::mem_row_major);
            }
        }
    } else {
        float* stage = (float*)gsm;
        for (int i = 0; i < 4; i++) {
            for (int j = 0; j < 2; j++) {
                nvcuda::wmma::store_matrix_sync(stage + (wm + i * 16) * 128 + wn + j * 16,
                                                acc[i][j], 128, nvcuda::wmma::mem_row_major);
            }
        }
        __syncthreads();
        int cb = bn - Nsplit;
        for (int t = tid; t < GBM * GBN; t += 256) {
            int r = t >> 7;
            int c = t & 127;
            float v = stage[t];
            __half hv = __float2half(v);
            size_t gi = (size_t)(bm + r) * ldh + cb + c;
            Chi[gi] = hv;
            Clo[gi] = __float2half(v - __half2float(hv));
        }
    }
}

// ---------------- RMSNorm + RoPE, one warp per (row, head) ----------------
// rows ordered m*(NHEADS+NKVH)+hy; hy<NHEADS -> q path, else k path.
__global__ __launch_bounds__(256) void rms_rope_kernel(const float* __restrict__ gain)
{
    const int warp = threadIdx.x >> 5;
    const int lane = threadIdx.x & 31;
    const int rid  = blockIdx.x * 8 + warp;
    const int m  = rid / (NHEADS + NKVH);
    const int hy = rid % (NHEADS + NKVH);
    const int b = m / T_SEQ;
    const int t = m % T_SEQ;
    const int isq = (hy < NHEADS) ? 1 : 0;
    const int h = isq ? hy : (hy - NHEADS);

    const float* src = isq ? (g_q + (size_t)m * DIM + h * HD)
                           : (g_kt + (size_t)m * RANK + h * HD);
    float4 xv = *(const float4*)(src + 4 * lane);
    float ss = xv.x * xv.x + xv.y * xv.y + xv.z * xv.z + xv.w * xv.w;
#pragma unroll
    for (int o = 16; o > 0; o >>= 1) ss += __shfl_xor_sync(0xffffffffu, ss, o);
    float rn = rsqrtf(ss * (1.0f / HD) + EPS_F);

    float a0 = xv.x * rn;
    float a1 = xv.y * rn;
    float a2 = xv.z * rn;
    float a3 = xv.w * rn;
    float p0 = __shfl_xor_sync(0xffffffffu, a0, 16);
    float p1 = __shfl_xor_sync(0xffffffffu, a1, 16);
    float p2 = __shfl_xor_sync(0xffffffffu, a2, 16);
    float p3 = __shfl_xor_sync(0xffffffffu, a3, 16);

    const int dd = (lane & 15) * 4;
    const float2* rp = g_rope + (size_t)t * 64 + dd;
    float2 c0 = rp[0];
    float2 c1 = rp[1];
    float2 c2 = rp[2];
    float2 c3 = rp[3];

    float g = isq ? gain[h] : 1.0f;
    float o0, o1, o2, o3;
    if (lane < 16) {
        o0 = (a0 * c0.x + p0 * c0.y) * g;
        o1 = (a1 * c1.x + p1 * c1.y) * g;
        o2 = (a2 * c2.x + p2 * c2.y) * g;
        o3 = (a3 * c3.x + p3 * c3.y) * g;
    } else {
        o0 = (a0 * c0.x - p0 * c0.y) * g;
        o1 = (a1 * c1.x - p1 * c1.y) * g;
        o2 = (a2 * c2.x - p2 * c2.y) * g;
        o3 = (a3 * c3.x - p3 * c3.y) * g;
    }

    __half h0 = __float2half(o0);
    __half h1 = __float2half(o1);
    __half h2 = __float2half(o2);
    __half h3 = __float2half(o3);
    if (isq) {
        size_t base = ((size_t)(b * NHEADS + h) * T_SEQ + t) * HD + 4 * lane;
        *(__half2*)(g_qah + base)     = __halves2half2(h0, h1);
        *(__half2*)(g_qah + base + 2) = __halves2half2(h2, h3);
        __half l0 = __float2half(o0 - __half2float(h0));
        __half l1 = __float2half(o1 - __half2float(h1));
        __half l2 = __float2half(o2 - __half2float(h2));
        __half l3 = __float2half(o3 - __half2float(h3));
        *(__half2*)(g_qal + base)     = __halves2half2(l0, l1);
        *(__half2*)(g_qal + base + 2) = __halves2half2(l2, l3);
    } else {
        size_t base = ((size_t)(b * NKVH + h) * T_SEQ + t) * HD + 4 * lane;
        *(__half2*)(g_kah + base)     = __halves2half2(h0, h1);
        *(__half2*)(g_kah + base + 2) = __halves2half2(h2, h3);
    }
}

// ---------------- Flash attention (all fp16 2-pass, fp32 softmax) ----------------
#define FBQ 64
#define FBK 64
#define QLD 136
#define PLD 72
#define SLD 68

#define OQH 0
#define OQL (OQH + FBQ * QLD * 2)
#define OKV (OQL + FBQ * QLD * 2)
#define KVTILE (FBK * QLD * 2)
#define KVSTG (3 * KVTILE)
#define OPH (OKV + 2 * KVSTG)
#define OSF (OPH + FBQ * PLD * 2)
#define OMR (OSF + FBQ * 128 * 4)
#define OLR (OMR + 256)
#define OAR (OLR + 256)
#define FA3_SMEM (OAR + 256)

__device__ __forceinline__ void fa_stage_load(
    char* smb, int s,
    const __half* ksh, const __half* vsh, const __half* vsl, int tid)
{
    char* st = smb + OKV + s * KVSTG;
    __half* sKh = (__half*)st;
    __half* sVh = (__half*)(st + KVTILE);
    __half* sVl = (__half*)(st + 2 * KVTILE);
    for (int i = 0; i < 4; i++) {
        int idx = tid + 256 * i;
        int r = idx >> 4;
        int c = (idx & 15) * 8;
        __pipeline_memcpy_async(sKh + r * QLD + c, ksh + (size_t)r * HD + c, 16);
        __pipeline_memcpy_async(sVh + r * QLD + c, vsh + (size_t)r * RANK + c, 16);
        __pipeline_memcpy_async(sVl + r * QLD + c, vsl + (size_t)r * RANK + c, 16);
    }
}

__global__ __launch_bounds__(256) void flash_mma(
    const __half* __restrict__ Qhi, const __half* __restrict__ Qlo,
    const __half* __restrict__ Khi,
    const __half* __restrict__ Vhi, const __half* __restrict__ Vlo,
    __half* __restrict__ Yh, __half* __restrict__ Yl)
{
    extern __shared__ char smb[];
    __half* sQh = (__half*)(smb + OQH);
    __half* sQl = (__half*)(smb + OQL);
    __half* sPh = (__half*)(smb + OPH);
    float* sSf  = (float*)(smb + OSF);
    float* sOd  = (float*)(smb + OSF);
    float* mrow = (float*)(smb + OMR);
    float* lrow = (float*)(smb + OLR);
    float* arow = (float*)(smb + OAR);

    const int tid  = threadIdx.x;
    const int warp = tid / 32;
    const int qt = (int)(gridDim.x - 1 - blockIdx.x);
    const int h  = blockIdx.y;
    const int b  = blockIdx.z;
    const int kh = h >> 2;
    const int q0 = qt * FBQ;

    const __half* Kh0 = Khi + ((size_t)(b * NKVH + kh) * T_SEQ) * HD;
    const __half* Vh0 = Vhi + (size_t)b * T_SEQ * RANK + kh * HD;
    const __half* Vl0 = Vlo + (size_t)b * T_SEQ * RANK + kh * HD;

    const __half* qsh = Qhi + ((size_t)(b * NHEADS + h) * T_SEQ + q0) * HD;
    const __half* qsl = Qlo + ((size_t)(b * NHEADS + h) * T_SEQ + q0) * HD;
    for (int i = tid; i < FBQ * HD / 8; i += 256) {
        int r = i >> 4;
        int c = (i & 15) * 8;
        *(uint4*)(sQh + r * QLD + c) = *(const uint4*)(qsh + (size_t)r * HD + c);
        *(uint4*)(sQl + r * QLD + c) = *(const uint4*)(qsl + (size_t)r * HD + c);
    }
    if (tid < 64) {
        mrow[tid] = -1e30f;
        lrow[tid] = 0.f;
    }

    float o[32];
#pragma unroll
    for (int j = 0; j < 32; j++) o[j] = 0.f;

    const int ro = tid >> 2;
    const int cq = tid & 3;

    fa_stage_load(smb, 0, Kh0, Vh0, Vl0, tid);
    __pipeline_commit();
    __syncthreads();

    for (int kt = 0; kt <= qt; kt++) {
        const int k0 = kt * FBK;
        if (kt < qt) {
            int k1 = (kt + 1) * FBK;
            fa_stage_load(smb, (kt + 1) & 1,
                          Kh0 + (size_t)k1 * HD,
                          Vh0 + (size_t)k1 * RANK, Vl0 + (size_t)k1 * RANK, tid);
            __pipeline_commit();
            __pipeline_wait_prior(1);
        } else {
            __pipeline_wait_prior(0);
        }
        __syncthreads();

        char* stg = smb + OKV + (size_t)(kt & 1) * KVSTG;
        __half* sKh = (__half*)stg;
        __half* sVh = (__half*)(stg + KVTILE);
        __half* sVl = (__half*)(stg + 2 * KVTILE);

        // ---- S = Q K^T (fp16 2-pass) ----
        {
            const int wm  = warp % 4;
            const int wc0 = (warp / 4) * 2;
            nvcuda::wmma::fragment<nvcuda::wmma::accumulator, 16, 16, 16, float> accs[2];
            for (int j = 0; j < 2; j++) nvcuda::wmma::fill_fragment(accs[j], 0.0f);
            for (int ks = 0; ks < HD; ks += 16) {
                nvcuda::wmma::fragment<nvcuda::wmma::matrix_a, 16, 16, 16,
                                       __half, nvcuda::wmma::row_major> fah;
                nvcuda::wmma::fragment<nvcuda::wmma::matrix_a, 16, 16, 16,
                                       __half, nvcuda::wmma::row_major> fal;
                nvcuda::wmma::load_matrix_sync(fah, sQh + (wm * 16) * QLD + ks, QLD);
                nvcuda::wmma::load_matrix_sync(fal, sQl + (wm * 16) * QLD + ks, QLD);
                for (int j = 0; j < 2; j++) {
                    nvcuda::wmma::fragment<nvcuda::wmma::matrix_b, 16, 16, 16,
                                           __half, nvcuda::wmma::col_major> fbh;
                    nvcuda::wmma::load_matrix_sync(fbh, sKh + ((wc0 + j) * 16) * QLD + ks, QLD);
                    nvcuda::wmma::mma_sync(accs[j], fah, fbh, accs[j]);
                    nvcuda::wmma::mma_sync(accs[j], fal, fbh, accs[j]);
                }
            }
            for (int j = 0; j < 2; j++) {
                nvcuda::wmma::store_matrix_sync(sSf + (wm * 16) * SLD + (wc0 + j) * 16,
                                                accs[j], SLD, nvcuda::wmma::mem_row_major);
            }
        }
        __syncthreads();

        // ---- online softmax ----
        {
            const int r  = tid >> 2;
            const int qq = tid & 3;
            const int qg = q0 + r;
            float mold = mrow[r];
            float vals[16];
            float rmax = mold;
#pragma unroll
            for (int j = 0; j < 16; j++) {
                int c = qq + 4 * j;
                float v = sSf[r * SLD + c] * SCALE_F;
                if (k0 + c > qg) v = -1e30f;
                vals[j] = v;
                rmax = fmaxf(rmax, v);
            }
            rmax = fmaxf(rmax, __shfl_xor_sync(0xffffffffu, rmax, 1));
            rmax = fmaxf(rmax, __shfl_xor_sync(0xffffffffu, rmax, 2));
            float alpha = __expf(mold - rmax);
            float rsum = 0.f;
#pragma unroll
            for (int j = 0; j < 16; j++) {
                int c = qq + 4 * j;
                float p = __expf(vals[j] - rmax);
                sPh[r * PLD + c] = __float2half(p);
                rsum += p;
            }
            rsum += __shfl_xor_sync(0xffffffffu, rsum, 1);
            rsum += __shfl_xor_sync(0xffffffffu, rsum, 2);
            if (qq == 0) {
                lrow[r] = lrow[r] * alpha + rsum;
                mrow[r] = rmax;
                arow[r] = alpha;
            }
        }
        __syncthreads();

        // ---- O_delta = P V (fp16 2-pass, warp tile 32x32) ----
        {
            const int wmP = (warp & 1) * 32;
            const int wnP = (warp >> 1) * 32;
            nvcuda::wmma::fragment<nvcuda::wmma::accumulator, 16, 16, 16, float> accd[2][2];
            for (int i = 0; i < 2; i++)
                for (int j = 0; j < 2; j++)
                    nvcuda::wmma::fill_fragment(accd[i][j], 0.0f);
            for (int kc = 0; kc < FBK; kc += 16) {
                nvcuda::wmma::fragment<nvcuda::wmma::matrix_a, 16, 16, 16,
                                       __half, nvcuda::wmma::row_major> pah[2];
                for (int i = 0; i < 2; i++) {
                    nvcuda::wmma::load_matrix_sync(pah[i],
                        sPh + (wmP + i * 16) * PLD + kc, PLD);
                }
                for (int j = 0; j < 2; j++) {
                    nvcuda::wmma::fragment<nvcuda::wmma::matrix_b, 16, 16, 16,
                                           __half, nvcuda::wmma::row_major> vbh;
                    nvcuda::wmma::fragment<nvcuda::wmma::matrix_b, 16, 16, 16,
                                           __half, nvcuda::wmma::row_major> vbl;
                    nvcuda::wmma::load_matrix_sync(vbh, sVh + kc * QLD + wnP + j * 16, QLD);
                    nvcuda::wmma::load_matrix_sync(vbl, sVl + kc * QLD + wnP + j * 16, QLD);
                    for (int i = 0; i < 2; i++) {
                        nvcuda::wmma::mma_sync(accd[i][j], pah[i], vbh, accd[i][j]);
                        nvcuda::wmma::mma_sync(accd[i][j], pah[i], vbl, accd[i][j]);
                    }
                }
            }
            for (int i = 0; i < 2; i++) {
                for (int j = 0; j < 2; j++) {
                    nvcuda::wmma::store_matrix_sync(
                        sOd + (wmP + i * 16) * 128 + wnP + j * 16,
                        accd[i][j], 128, nvcuda::wmma::mem_row_major);
                }
            }
        }
        __syncthreads();

        {
            float alpha = arow[ro];
            const float* od = sOd + ro * 128 + cq * 32;
#pragma unroll
            for (int j = 0; j < 32; j++) o[j] = o[j] * alpha + od[j];
        }
        __syncthreads();
    }

    float inv = 1.0f / lrow[ro];
    size_t yb = ((size_t)(b * T_SEQ) + q0 + ro) * DIM + h * HD + cq * 32;
#pragma unroll
    for (int j = 0; j < 32; j++) {
        float v = o[j] * inv;
        __half hv = __float2half(v);
        Yh[yb + j] = hv;
        Yl[yb + j] = __float2half(v - __half2float(hv));
    }
}

// ---------------- Launch ----------------
extern "C" void kernel_launch(void* const* d_in, const int* in_sizes, int n_in,
                              void* d_out, int out_size)
{
    (void)in_sizes;
    (void)n_in;
    (void)out_size;
    const float* x     = (const float*)d_in[0];
    const float* Wq    = (const float*)d_in[1];
    const float* Wdown = (const float*)d_in[2];
    const float* Wkup  = (const float*)d_in[3];
    const float* Wvup  = (const float*)d_in[4];
    const float* Wproj = (const float*)d_in[5];
    const float* qgain = (const float*)d_in[6];
    float* out = (float*)d_out;

    float* q;
    float* kt;
    cudaGetSymbolAddress((void**)&q,  g_q);
    cudaGetSymbolAddress((void**)&kt, g_kt);

    __half* xhi;
    __half* xlo;
    __half* lhi;
    __half* llo;
    __half* yhi;
    __half* ylo;
    __half* wqd;
    __half* wkv;
    __half* wph;
    cudaGetSymbolAddress((void**)&xhi, g_xhi);
    cudaGetSymbolAddress((void**)&xlo, g_xlo);
    cudaGetSymbolAddress((void**)&lhi, g_lhi);
    cudaGetSymbolAddress((void**)&llo, g_llo);
    cudaGetSymbolAddress((void**)&yhi, g_yhi);
    cudaGetSymbolAddress((void**)&ylo, g_ylo);
    cudaGetSymbolAddress((void**)&wqd, g_wqd);
    cudaGetSymbolAddress((void**)&wkv, g_wkv);
    cudaGetSymbolAddress((void**)&wph, g_wph);

    __half* qah;
    __half* qal;
    __half* kah;
    __half* vth;
    __half* vtl;
    cudaGetSymbolAddress((void**)&qah, g_qah);
    cudaGetSymbolAddress((void**)&qal, g_qal);
    cudaGetSymbolAddress((void**)&kah, g_kah);
    cudaGetSymbolAddress((void**)&vth, g_vth);
    cudaGetSymbolAddress((void**)&vtl, g_vtl);

    cudaFuncSetAttribute(gemm_h, cudaFuncAttributeMaxDynamicSharedMemorySize,
                         GSMEM_BYTES);
    cudaFuncSetAttribute(gemm_h_mix, cudaFuncAttributeMaxDynamicSharedMemorySize,
                         GSMEM_BYTES);
    cudaFuncSetAttribute(flash_mma, cudaFuncAttributeMaxDynamicSharedMemorySize,
                         FA3_SMEM);

    long long ptot = PREP_TOTAL;
    prep_kernel<<<(int)((ptot + 255) / 256), 256>>>(x, Wq, Wdown, Wkup, Wvup, Wproj);

    gemm_h_mix<<<dim3((DIM + RANK) / GBN, M_ROWS / GBM), 256, GSMEM_BYTES>>>(
        xhi, xlo, wqd, q, lhi, llo, M_ROWS, DIM + RANK, DIM, DIM, DIM, RANK);
    gemm_h_mix<<<dim3((2 * RANK) / GBN, M_ROWS / GBM), 256, GSMEM_BYTES>>>(
        lhi, llo, wkv, kt, vth, vtl, M_ROWS, 2 * RANK, RANK, RANK, RANK, RANK);

    // one warp per (row, head): M_ROWS*(NHEADS+NKVH) rows, 8 warps per block
    rms_rope_kernel<<<(M_ROWS * (NHEADS + NKVH)) / 8, 256>>>(qgain);

    flash_mma<<<dim3(T_SEQ / FBQ, NHEADS, BATCH), 256, FA3_SMEM>>>(qah, qal, kah,
                                                                   vth, vtl, yhi, ylo);

    gemm_h<<<dim3(DIM / GBN, M_ROWS / GBM), 256, GSMEM_BYTES>>>(
        yhi, ylo, wph, out, M_ROWS, DIM, DIM);
}